// round 14
// baseline (speedup 1.0000x reference)
#include <cuda_runtime.h>
#include <cuda_fp16.h>
#include <cstdint>
#include <cstddef>

#define BATCH 4
#define NQ    2048
#define NK    2048
#define EMB   512
#define NH    8
#define HD    64
#define NTOK  (BATCH * NQ)
#define BHN   (BATCH * NH)

// ---------------- device-global scratch ---------------------------------------
__device__ __half g_qn [NTOK * EMB];
__device__ __half g_kvn[NTOK * EMB];
__device__ __half g_q  [NTOK * EMB];          // pre-scaled by 0.125*log2(e)
__device__ __half g_k  [NTOK * EMB];          // COMPACTED rows per batch
__device__ __half g_vt [BHN * HD * NK];       // V^T per (b,h): [d][compacted key]
__device__ __half g_ctx[NTOK * EMB];
__device__ __half g_wt [4 * EMB * EMB];       // W^T, k-major rows
__device__ unsigned long long g_mbits[(size_t)BATCH * NQ * (NK / 64)];
__device__ int g_kidx[BATCH * NK];
__device__ int g_nvalid[BATCH];
__device__ int g_nkt[BATCH];
__device__ int g_is_byte[2];

// ---------------- streams/events for graph-parallel branches -------------------
struct StreamInit {
    cudaStream_t s2 = nullptr, s3 = nullptr;
    cudaEvent_t eFork = nullptr, eCompact = nullptr, eMask = nullptr, eWt = nullptr;
    bool ok = false;
    StreamInit() {
        if (cudaStreamCreateWithFlags(&s2, cudaStreamNonBlocking) != cudaSuccess) return;
        if (cudaStreamCreateWithFlags(&s3, cudaStreamNonBlocking) != cudaSuccess) return;
        if (cudaEventCreateWithFlags(&eFork, cudaEventDisableTiming) != cudaSuccess) return;
        if (cudaEventCreateWithFlags(&eCompact, cudaEventDisableTiming) != cudaSuccess) return;
        if (cudaEventCreateWithFlags(&eMask, cudaEventDisableTiming) != cudaSuccess) return;
        if (cudaEventCreateWithFlags(&eWt, cudaEventDisableTiming) != cudaSuccess) return;
        ok = true;
    }
};
static StreamInit g_si;

// ---------------- PTX helpers --------------------------------------------------
__device__ __forceinline__ uint32_t sptr(const void* p) {
    uint32_t a;
    asm("{ .reg .u64 t; cvta.to.shared.u64 t, %1; cvt.u32.u64 %0, t; }"
        : "=r"(a) : "l"(p));
    return a;
}
__device__ __forceinline__ uint32_t h2ex2(uint32_t x) {
    uint32_t r;
    asm("ex2.approx.f16x2 %0, %1;" : "=r"(r) : "r"(x));
    return r;
}

#define MMA_F16(C, A, B) \
    asm volatile( \
        "mma.sync.aligned.m16n8k16.row.col.f32.f16.f16.f32 " \
        "{%0,%1,%2,%3}, {%4,%5,%6,%7}, {%8,%9}, {%0,%1,%2,%3};" \
        : "+f"((C)[0]), "+f"((C)[1]), "+f"((C)[2]), "+f"((C)[3]) \
        : "r"((A)[0]), "r"((A)[1]), "r"((A)[2]), "r"((A)[3]), \
          "r"((B)[0]), "r"((B)[1]))

#define LDSM4(R0, R1, R2, R3, ADDR) \
    asm volatile("ldmatrix.sync.aligned.m8n8.x4.shared.b16 {%0,%1,%2,%3}, [%4];" \
        : "=r"(R0), "=r"(R1), "=r"(R2), "=r"(R3) : "r"(ADDR))

#define CP16(DST, SRC) \
    asm volatile("cp.async.cg.shared.global [%0], [%1], 16;" \
        :: "r"(DST), "l"(SRC))
#define CP_COMMIT() asm volatile("cp.async.commit_group;" ::: "memory")
#define CP_WAIT0()  asm volatile("cp.async.wait_group 0;" ::: "memory")

// ---------------- fp16 GEMM mainloop: BK=64, cp.async double-buffered ----------
#define GSMEM 73728
__device__ __forceinline__ void gemm16_mainloop(
        const __half* __restrict__ A, const int* __restrict__ ridx,
        const __half* __restrict__ B, float (&c)[2][8][4], char* sm) {
    const int tid = threadIdx.x;
    const int lane = tid & 31, wid = tid >> 5;
    const int wm = wid & 3, wn = wid >> 2;
    const uint32_t s0 = sptr(sm);

    #pragma unroll
    for (int mt = 0; mt < 2; mt++)
        #pragma unroll
        for (int nt = 0; nt < 8; nt++)
            #pragma unroll
            for (int j = 0; j < 4; j++) c[mt][nt][j] = 0.0f;

    const uint32_t a_base = s0 +
        (wm * 32 + ((lane & 8) ? 8 : 0) + (lane & 7)) * 144 + ((lane & 16) ? 16 : 0);
    const uint32_t b_base = s0 + 18432 +
        (wn * 64 + ((lane & 16) ? 8 : 0) + (lane & 7)) * 144 + ((lane & 8) ? 16 : 0);

    const int rbase = tid >> 3;
    const int fh = (tid & 7) * 8;
    const uint32_t fB = (tid & 7) * 16;
    int ar[4];
    #pragma unroll
    for (int i = 0; i < 4; i++)
        ar[i] = ridx ? ridx[rbase + 32 * i] : (rbase + 32 * i);

    #pragma unroll
    for (int i = 0; i < 4; i++) {
        int r = rbase + 32 * i;
        CP16(s0 + r * 144 + fB, A + (size_t)ar[i] * EMB + fh);
        CP16(s0 + 18432 + r * 144 + fB, B + (size_t)r * EMB + fh);
    }
    CP_COMMIT();

    for (int ch = 0; ch < 8; ch++) {
        const int buf = ch & 1;
        CP_WAIT0();
        __syncthreads();
        if (ch + 1 < 8) {
            const uint32_t nb = (uint32_t)((ch + 1) & 1) * 36864u;
            const int co = (ch + 1) * 64 + fh;
            #pragma unroll
            for (int i = 0; i < 4; i++) {
                int r = rbase + 32 * i;
                CP16(s0 + nb + r * 144 + fB, A + (size_t)ar[i] * EMB + co);
                CP16(s0 + nb + 18432 + r * 144 + fB, B + (size_t)r * EMB + co);
            }
            CP_COMMIT();
        }
        const uint32_t ab = a_base + buf * 36864u;
        const uint32_t bb = b_base + buf * 36864u;
        #pragma unroll
        for (int ks = 0; ks < 4; ks++) {
            uint32_t a[2][4], b[8][2];
            #pragma unroll
            for (int mt = 0; mt < 2; mt++)
                LDSM4(a[mt][0], a[mt][1], a[mt][2], a[mt][3],
                      ab + mt * 16 * 144 + ks * 32);
            #pragma unroll
            for (int p = 0; p < 4; p++)
                LDSM4(b[2*p][0], b[2*p][1], b[2*p+1][0], b[2*p+1][1],
                      bb + p * 16 * 144 + ks * 32);
            #pragma unroll
            for (int mt = 0; mt < 2; mt++)
                #pragma unroll
                for (int nt = 0; nt < 8; nt++)
                    MMA_F16(c[mt][nt], a[mt], b[nt]);
        }
    }
}

// Q/K/V projections. z=0: Q (scaled 0.125*log2e), z=1: K (gathered), z=2: V^T.
__global__ void __launch_bounds__(256, 2) proj_qkv_kernel(
        const __half* __restrict__ qn, const __half* __restrict__ kvn,
        const __half* __restrict__ wt,
        const float* __restrict__ bq, const float* __restrict__ bk,
        const float* __restrict__ bv,
        __half* __restrict__ q, __half* __restrict__ k,
        __half* __restrict__ vt) {
    extern __shared__ __align__(16) char smqkv[];
    const int z = blockIdx.z;
    const size_t bm = (size_t)blockIdx.y * 128, bn = (size_t)blockIdx.x * 128;
    const int bb = (int)(bm >> 11);
    const int rloc = (int)(bm & 2047);

    const int* ridx = nullptr;
    const __half* A;
    if (z == 0) {
        A = qn + bm * EMB;
    } else {
        if (rloc >= g_nkt[bb] * 64) return;
        A = kvn + (size_t)bb * 2048 * EMB;
        ridx = g_kidx + bb * NK + rloc;
    }
    const __half* B = wt + (size_t)z * EMB * EMB + bn * EMB;
    float c[2][8][4];
    gemm16_mainloop(A, ridx, B, c, smqkv);

    const int tid = threadIdx.x, lane = tid & 31, wid = tid >> 5;
    const int wm = wid & 3, wn = wid >> 2, g = lane >> 2, t = lane & 3;
    const float* bias = (z == 0) ? bq : (z == 1) ? bk : bv;
    const float scale = (z == 0) ? 0.1803368801111244f : 1.0f;  // 0.125*log2(e)

    if (z < 2) {
        #pragma unroll
        for (int mt = 0; mt < 2; mt++) {
            #pragma unroll
            for (int nt = 0; nt < 8; nt++) {
                int m   = (int)bm + wm * 32 + mt * 16 + g;
                int col = (int)bn + wn * 64 + nt * 8 + 2 * t;
                float b0 = bias[col], b1 = bias[col + 1];
                float v0 = (c[mt][nt][0] + b0) * scale;
                float v1 = (c[mt][nt][1] + b1) * scale;
                float v2 = (c[mt][nt][2] + b0) * scale;
                float v3 = (c[mt][nt][3] + b1) * scale;
                __half* dst = (z == 0) ? q : k;
                *(half2*)(dst + (size_t)m * EMB + col) = __floats2half2_rn(v0, v1);
                *(half2*)(dst + (size_t)(m + 8) * EMB + col) = __floats2half2_rn(v2, v3);
            }
        }
    } else {
        __half* smT = (__half*)smqkv;
        __syncthreads();
        #pragma unroll
        for (int mt = 0; mt < 2; mt++) {
            #pragma unroll
            for (int nt = 0; nt < 8; nt++) {
                int m   = wm * 32 + mt * 16 + g;
                int col = wn * 64 + nt * 8 + 2 * t;
                float b0 = bias[(int)bn + col], b1 = bias[(int)bn + col + 1];
                smT[col * 136 + m]           = __float2half_rn(c[mt][nt][0] + b0);
                smT[(col + 1) * 136 + m]     = __float2half_rn(c[mt][nt][1] + b1);
                smT[col * 136 + m + 8]       = __float2half_rn(c[mt][nt][2] + b0);
                smT[(col + 1) * 136 + m + 8] = __float2half_rn(c[mt][nt][3] + b1);
            }
        }
        __syncthreads();
        int col = tid >> 1;
        int mo  = (tid & 1) * 64;
        int gc  = (int)bn + col;
        int h = gc >> 6, d = gc & 63;
        size_t orow = ((size_t)(bb * NH + h) * HD + d) * NK + (size_t)rloc + mo;
        const uint4* srcp = (const uint4*)(smT + col * 136 + mo);
        uint4* dstp = (uint4*)(vt + orow);
        #pragma unroll
        for (int j = 0; j < 8; j++) dstp[j] = srcp[j];
    }
}

__global__ void __launch_bounds__(256, 2) proj_o_kernel(
        const __half* __restrict__ ctx, const __half* __restrict__ wt,
        const float* __restrict__ bo, float* __restrict__ out) {
    extern __shared__ __align__(16) char smo[];
    const size_t bm = (size_t)blockIdx.y * 128, bn = (size_t)blockIdx.x * 128;
    float c[2][8][4];
    gemm16_mainloop(ctx + bm * EMB, nullptr,
                    wt + 3ull * EMB * EMB + bn * EMB, c, smo);

    const int tid = threadIdx.x, lane = tid & 31, wid = tid >> 5;
    const int wm = wid & 3, wn = wid >> 2, g = lane >> 2, t = lane & 3;
    #pragma unroll
    for (int mt = 0; mt < 2; mt++) {
        #pragma unroll
        for (int nt = 0; nt < 8; nt++) {
            int m   = (int)bm + wm * 32 + mt * 16 + g;
            int col = (int)bn + wn * 64 + nt * 8 + 2 * t;
            float b0 = bo[col], b1 = bo[col + 1];
            *(float2*)(out + (size_t)m * EMB + col) =
                make_float2(c[mt][nt][0] + b0, c[mt][nt][1] + b1);
            *(float2*)(out + (size_t)(m + 8) * EMB + col) =
                make_float2(c[mt][nt][2] + b0, c[mt][nt][3] + b1);
        }
    }
}

// ---------------- fused flash attention (scalar l from pfrag) -------------------
// Dynamic smem (bytes): Ks 2x9216 at 0; Vs 2x9216 at 18432. Total 36864.
#define FATTN_SMEM 36864
__global__ void __launch_bounds__(256, 2) fattn_kernel(
        const __half* __restrict__ Qp, const __half* __restrict__ Kp,
        const __half* __restrict__ Vtp,
        const unsigned long long* __restrict__ mbits,
        __half* __restrict__ ctx) {
    extern __shared__ __align__(16) __half smd[];

    const int tid = threadIdx.x;
    const int lane = tid & 31, w = tid >> 5;
    const int g = lane >> 2, t = lane & 3;
    const int qt = blockIdx.x, bh = blockIdx.y;
    const int b = bh >> 3, h = bh & 7;
    const int row0 = w * 16 + g, row1 = row0 + 8;
    const int nkt = g_nkt[b];

    const uint32_t ks_smem = sptr(smd);
    const uint32_t vs_smem = ks_smem + 18432;
    const uint32_t lrow = ((lane & 16) ? 8 : 0) + (lane & 7);
    const uint32_t k_base = ks_smem + lrow * 144 + ((lane & 8) ? 16 : 0);
    const uint32_t v_base = vs_smem + lrow * 144 + ((lane & 8) ? 16 : 0);

    uint32_t qa[4][4];
    {
        const __half* q0 = Qp + (size_t)(b * NQ + qt * 128 + row0) * EMB + h * HD;
        const __half* q1 = Qp + (size_t)(b * NQ + qt * 128 + row1) * EMB + h * HD;
        #pragma unroll
        for (int ks = 0; ks < 4; ks++) {
            qa[ks][0] = *(const uint32_t*)(q0 + ks * 16 + 2 * t);
            qa[ks][1] = *(const uint32_t*)(q1 + ks * 16 + 2 * t);
            qa[ks][2] = *(const uint32_t*)(q0 + ks * 16 + 2 * t + 8);
            qa[ks][3] = *(const uint32_t*)(q1 + ks * 16 + 2 * t + 8);
        }
    }

    float m0 = -40.0f, m1 = -40.0f;
    float l0 = 0.0f, l1 = 0.0f;
    float acc[8][4];
    #pragma unroll
    for (int nt = 0; nt < 8; nt++)
        #pragma unroll
        for (int j = 0; j < 4; j++) acc[nt][j] = 0.0f;

    const unsigned long long* mb0 =
        mbits + ((size_t)b * NQ + qt * 128 + row0) * (NK / 64);
    const unsigned long long* mb1 =
        mbits + ((size_t)b * NQ + qt * 128 + row1) * (NK / 64);

    const __half* Kbase  = Kp + ((size_t)b * NK) * EMB + h * HD;
    const __half* Vtbase = Vtp + (size_t)bh * HD * NK;

    if (nkt > 0) {
        #pragma unroll
        for (int i = 0; i < 2; i++) {
            int s = tid + i * 256;
            int r = s >> 3, f = s & 7;
            CP16(ks_smem + r * 144 + f * 16, Kbase + (size_t)r * EMB + f * 8);
            CP16(vs_smem + r * 144 + f * 16, Vtbase + (size_t)r * NK + f * 8);
        }
        CP_COMMIT();
    }

    for (int kt = 0; kt < nkt; kt++) {
        const int buf = kt & 1;
        unsigned long long w0 = mb0[kt], w1 = mb1[kt];
        CP_WAIT0();
        __syncthreads();

        if (kt + 1 < nkt) {
            int k0n = (kt + 1) * 64;
            int nbuf = buf ^ 1;
            #pragma unroll
            for (int i = 0; i < 2; i++) {
                int s = tid + i * 256;
                int r = s >> 3, f = s & 7;
                CP16(ks_smem + nbuf * 9216 + r * 144 + f * 16,
                     Kbase + (size_t)(k0n + r) * EMB + f * 8);
                CP16(vs_smem + nbuf * 9216 + r * 144 + f * 16,
                     Vtbase + (size_t)r * NK + k0n + f * 8);
            }
            CP_COMMIT();
        }

        // S = Q @ K^T (log2 units)
        float sc[8][4];
        #pragma unroll
        for (int nt = 0; nt < 8; nt++)
            #pragma unroll
            for (int j = 0; j < 4; j++) sc[nt][j] = 0.0f;
        const uint32_t kb = k_base + buf * 9216;
        #pragma unroll
        for (int ks = 0; ks < 4; ks++) {
            uint32_t bf[8][2];
            #pragma unroll
            for (int p = 0; p < 4; p++)
                LDSM4(bf[2*p][0], bf[2*p][1], bf[2*p+1][0], bf[2*p+1][1],
                      kb + p * 16 * 144 + ks * 32);
            #pragma unroll
            for (int nt = 0; nt < 8; nt++)
                MMA_F16(sc[nt], qa[ks], bf[nt]);
        }

        // mask + tile max
        float tm0 = -1e30f, tm1 = -1e30f;
        #pragma unroll
        for (int nt = 0; nt < 8; nt++) {
            int c0 = nt * 8 + 2 * t;
            sc[nt][0] = ((w0 >> c0) & 1)       ? sc[nt][0] : -1e30f;
            sc[nt][1] = ((w0 >> (c0 + 1)) & 1) ? sc[nt][1] : -1e30f;
            sc[nt][2] = ((w1 >> c0) & 1)       ? sc[nt][2] : -1e30f;
            sc[nt][3] = ((w1 >> (c0 + 1)) & 1) ? sc[nt][3] : -1e30f;
            tm0 = fmaxf(tm0, fmaxf(sc[nt][0], sc[nt][1]));
            tm1 = fmaxf(tm1, fmaxf(sc[nt][2], sc[nt][3]));
        }
        tm0 = fmaxf(tm0, __shfl_xor_sync(0xffffffffu, tm0, 1));
        tm0 = fmaxf(tm0, __shfl_xor_sync(0xffffffffu, tm0, 2));
        tm1 = fmaxf(tm1, __shfl_xor_sync(0xffffffffu, tm1, 1));
        tm1 = fmaxf(tm1, __shfl_xor_sync(0xffffffffu, tm1, 2));

        float mn0 = fmaxf(m0, tm0), mn1 = fmaxf(m1, tm1);
        if (__any_sync(0xffffffffu, (mn0 > m0) | (mn1 > m1))) {
            float corr0 = exp2f(m0 - mn0);
            float corr1 = exp2f(m1 - mn1);
            #pragma unroll
            for (int nt = 0; nt < 8; nt++) {
                acc[nt][0] *= corr0; acc[nt][1] *= corr0;
                acc[nt][2] *= corr1; acc[nt][3] *= corr1;
            }
            l0 *= corr0;  l1 *= corr1;
            m0 = mn0;  m1 = mn1;
        }

        // P in registers (FA-2 layout identity)
        uint32_t pfrag[4][4];
        #pragma unroll
        for (int ks = 0; ks < 4; ks++) {
            half2 h00 = __floats2half2_rn(sc[2*ks][0] - m0, sc[2*ks][1] - m0);
            half2 h01 = __floats2half2_rn(sc[2*ks][2] - m1, sc[2*ks][3] - m1);
            half2 h10 = __floats2half2_rn(sc[2*ks+1][0] - m0, sc[2*ks+1][1] - m0);
            half2 h11 = __floats2half2_rn(sc[2*ks+1][2] - m1, sc[2*ks+1][3] - m1);
            pfrag[ks][0] = h2ex2(*(uint32_t*)&h00);
            pfrag[ks][1] = h2ex2(*(uint32_t*)&h01);
            pfrag[ks][2] = h2ex2(*(uint32_t*)&h10);
            pfrag[ks][3] = h2ex2(*(uint32_t*)&h11);
        }

        // scalar row sums from pfrag (fp32 accumulate; FMA pipe overlaps tensor)
        {
            float ps0 = 0.0f, ps1 = 0.0f;
            #pragma unroll
            for (int ks = 0; ks < 4; ks++) {
                float2 a0 = __half22float2(*(half2*)&pfrag[ks][0]);
                float2 a2 = __half22float2(*(half2*)&pfrag[ks][2]);
                float2 b1 = __half22float2(*(half2*)&pfrag[ks][1]);
                float2 b3 = __half22float2(*(half2*)&pfrag[ks][3]);
                ps0 += (a0.x + a0.y) + (a2.x + a2.y);
                ps1 += (b1.x + b1.y) + (b3.x + b3.y);
            }
            ps0 += __shfl_xor_sync(0xffffffffu, ps0, 1);
            ps0 += __shfl_xor_sync(0xffffffffu, ps0, 2);
            ps1 += __shfl_xor_sync(0xffffffffu, ps1, 1);
            ps1 += __shfl_xor_sync(0xffffffffu, ps1, 2);
            l0 += ps0;  l1 += ps1;
        }

        // O += P @ V
        const uint32_t vb = v_base + buf * 9216;
        #pragma unroll
        for (int ks = 0; ks < 4; ks++) {
            uint32_t bv[8][2];
            #pragma unroll
            for (int p = 0; p < 4; p++)
                LDSM4(bv[2*p][0], bv[2*p][1], bv[2*p+1][0], bv[2*p+1][1],
                      vb + p * 16 * 144 + ks * 32);
            #pragma unroll
            for (int nt = 0; nt < 8; nt++)
                MMA_F16(acc[nt], pfrag[ks], bv[nt]);
        }
    }

    float inv0 = (l0 > 0.0f) ? (1.0f / l0) : 0.0f;
    float inv1 = (l1 > 0.0f) ? (1.0f / l1) : 0.0f;
    __half* o0 = ctx + (size_t)(b * NQ + qt * 128 + row0) * EMB + h * HD;
    __half* o1 = ctx + (size_t)(b * NQ + qt * 128 + row1) * EMB + h * HD;
    #pragma unroll
    for (int nt = 0; nt < 8; nt++) {
        int c0 = nt * 8 + 2 * t;
        *(half2*)(o0 + c0) = __floats2half2_rn(acc[nt][0] * inv0, acc[nt][1] * inv0);
        *(half2*)(o1 + c0) = __floats2half2_rn(acc[nt][2] * inv1, acc[nt][3] * inv1);
    }
}

// ---------------- mask dtype sniff ---------------------------------------------
__global__ void detect_mask_kernel(const unsigned char* kvm_raw,
                                   const unsigned char* spm_raw) {
    __shared__ int found[2];
    if (threadIdx.x == 0) { found[0] = 0; found[1] = 0; }
    __syncthreads();
    for (int i = threadIdx.x; i < 8192; i += blockDim.x) {
        if ((i & 3) != 0) {
            if (kvm_raw[i]) atomicOr(&found[0], 1);
            if (spm_raw[i]) atomicOr(&found[1], 1);
        }
    }
    __syncthreads();
    if (threadIdx.x == 0) { g_is_byte[0] = found[0]; g_is_byte[1] = found[1]; }
}

// ---------------- kv_mask stream compaction -------------------------------------
__global__ void compact_idx_kernel(const void* kvm_raw) {
    const int b = blockIdx.x;
    const int tid = threadIdx.x;
    const int lane = tid & 31, w = tid >> 5;
    __shared__ int base;
    __shared__ int wstart[8];
    __shared__ int wcnt[8];
    if (tid == 0) base = 0;
    __syncthreads();
    const bool kb = g_is_byte[0] != 0;
    for (int c0 = 0; c0 < NK; c0 += 256) {
        int kk = c0 + tid;
        bool v = kb ? (((const unsigned char*)kvm_raw)[b * NK + kk] != 0)
                    : (((const int*)kvm_raw)[b * NK + kk] != 0);
        unsigned bal = __ballot_sync(0xffffffffu, v);
        if (lane == 0) wcnt[w] = __popc(bal);
        __syncthreads();
        if (tid == 0) {
            int s = base;
            #pragma unroll
            for (int i = 0; i < 8; i++) { wstart[i] = s; s += wcnt[i]; }
            base = s;
        }
        __syncthreads();
        if (v)
            g_kidx[b * NK + wstart[w] + __popc(bal & ((1u << lane) - 1))] = kk;
        __syncthreads();
    }
    int nv = base;
    for (int c = nv + tid; c < NK; c += 256) g_kidx[b * NK + c] = 0;
    if (tid == 0) {
        g_nvalid[b] = nv;
        g_nkt[b] = (nv + 63) >> 6;
    }
}

// ---------------- sparse-mask bits (coalesced via smem) --------------------------
__global__ void __launch_bounds__(256) mask_bits_kernel(const void* spm_raw) {
    __shared__ unsigned char sp_sm[2048];
    __shared__ uint32_t wb[64];
    const int bq = blockIdx.x;
    const int b = bq >> 11;
    const int tid = threadIdx.x;

    if (g_is_byte[1]) {
        const uint32_t* sp = (const uint32_t*)
            ((const unsigned char*)spm_raw + (size_t)bq * NK);
        for (int i = tid; i < 512; i += 256) {
            uint32_t v = sp[i];
            sp_sm[i * 4 + 0] = (v & 0x000000ffu) ? 1 : 0;
            sp_sm[i * 4 + 1] = (v & 0x0000ff00u) ? 1 : 0;
            sp_sm[i * 4 + 2] = (v & 0x00ff0000u) ? 1 : 0;
            sp_sm[i * 4 + 3] = (v & 0xff000000u) ? 1 : 0;
        }
    } else {
        const int* sp = (const int*)spm_raw + (size_t)bq * NK;
        for (int i = tid; i < 2048; i += 256)
            sp_sm[i] = sp[i] ? 1 : 0;
    }
    __syncthreads();

    const int nv = g_nvalid[b];
    const int* kidx = g_kidx + b * NK;
    #pragma unroll
    for (int i = 0; i < 8; i++) {
        int c = i * 256 + tid;
        bool bit = (c < nv) && (sp_sm[kidx[c]] != 0);
        unsigned bal = __ballot_sync(0xffffffffu, bit);
        if ((tid & 31) == 0) wb[i * 8 + (tid >> 5)] = bal;
    }
    __syncthreads();
    if (tid < 32) {
        int i = tid >> 2, wp = (tid & 3) * 2;
        uint64_t wv = (uint64_t)wb[i * 8 + wp] |
                      ((uint64_t)wb[i * 8 + wp + 1] << 32);
        g_mbits[(size_t)bq * 32 + tid] = wv;
    }
}

// ---------------- LayerNorm (warp-per-row, shuffle-only) ------------------------
__global__ void __launch_bounds__(256) lnorm_kernel(
        const float* __restrict__ xq, const float* __restrict__ xkv,
        const float* __restrict__ gq, const float* __restrict__ bq,
        const float* __restrict__ gkv, const float* __restrict__ bkv,
        __half* __restrict__ yq, __half* __restrict__ ykv) {
    const int row = blockIdx.x * 8 + (threadIdx.x >> 5);
    const int lane = threadIdx.x & 31;
    const float* x = blockIdx.y ? xkv : xq;
    const float* g = blockIdx.y ? gkv : gq;
    const float* b = blockIdx.y ? bkv : bq;
    __half* y      = blockIdx.y ? ykv : yq;

    const float4* xr = (const float4*)(x + (size_t)row * EMB);
    float4 v[4];
    float s = 0.0f, s2 = 0.0f;
    #pragma unroll
    for (int j = 0; j < 4; j++) {
        v[j] = xr[lane + 32 * j];
        s  += v[j].x + v[j].y + v[j].z + v[j].w;
        s2 += v[j].x*v[j].x + v[j].y*v[j].y + v[j].z*v[j].z + v[j].w*v[j].w;
    }
    #pragma unroll
    for (int o = 16; o > 0; o >>= 1) {
        s  += __shfl_xor_sync(0xffffffffu, s,  o);
        s2 += __shfl_xor_sync(0xffffffffu, s2, o);
    }
    float mu  = s * (1.0f / EMB);
    float var = s2 * (1.0f / EMB) - mu * mu;
    float inv = rsqrtf(var + 1e-5f);
    #pragma unroll
    for (int j = 0; j < 4; j++) {
        float4 gg = ((const float4*)g)[lane + 32 * j];
        float4 bb = ((const float4*)b)[lane + 32 * j];
        half2 h0 = __floats2half2_rn((v[j].x - mu) * inv * gg.x + bb.x,
                                     (v[j].y - mu) * inv * gg.y + bb.y);
        half2 h1 = __floats2half2_rn((v[j].z - mu) * inv * gg.z + bb.z,
                                     (v[j].w - mu) * inv * gg.w + bb.w);
        uint2 o2 = make_uint2(*(uint32_t*)&h0, *(uint32_t*)&h1);
        *(uint2*)(y + (size_t)row * EMB + (lane + 32 * j) * 4) = o2;
    }
}

// ---------------- weight transpose ------------------------------------------------
__global__ void wt_kernel(const float* __restrict__ Wq,
                          const float* __restrict__ Wk,
                          const float* __restrict__ Wv,
                          const float* __restrict__ Wo,
                          __half* __restrict__ Wt) {
    __shared__ float tile[32][33];
    int z = blockIdx.z;
    const float* W = (z == 0) ? Wq : (z == 1) ? Wk : (z == 2) ? Wv : Wo;
    __half* dst = Wt + (size_t)z * EMB * EMB;
    int bx = blockIdx.x * 32, by = blockIdx.y * 32;
    int tx = threadIdx.x, ty = threadIdx.y;
    #pragma unroll
    for (int i = 0; i < 4; i++)
        tile[ty + i * 8][tx] = W[(size_t)(by + ty + i * 8) * EMB + bx + tx];
    __syncthreads();
    #pragma unroll
    for (int i = 0; i < 4; i++)
        dst[(size_t)(bx + ty + i * 8) * EMB + by + tx] =
            __float2half_rn(tile[tx][ty + i * 8]);
}

// ---------------- launch ----------------------------------------------------------
extern "C" void kernel_launch(void* const* d_in, const int* in_sizes, int n_in,
                              void* d_out, int out_size) {
    const float* query     = (const float*)d_in[0];
    const float* key_value = (const float*)d_in[1];
    const void*  kvm_raw   = d_in[2];
    const void*  spm_raw   = d_in[3];
    const float* ln_q_g  = (const float*)d_in[4];
    const float* ln_q_b  = (const float*)d_in[5];
    const float* ln_kv_g = (const float*)d_in[6];
    const float* ln_kv_b = (const float*)d_in[7];
    const float* Wq = (const float*)d_in[8];
    const float* bq = (const float*)d_in[9];
    const float* Wk = (const float*)d_in[10];
    const float* bk = (const float*)d_in[11];
    const float* Wv = (const float*)d_in[12];
    const float* bv = (const float*)d_in[13];
    const float* Wo = (const float*)d_in[14];
    const float* bo = (const float*)d_in[15];
    float* out = (float*)d_out;

    void *p_qn, *p_kvn, *p_q, *p_k, *p_vt, *p_ctx, *p_wt, *p_mb;
    cudaGetSymbolAddress(&p_qn,  g_qn);
    cudaGetSymbolAddress(&p_kvn, g_kvn);
    cudaGetSymbolAddress(&p_q,   g_q);
    cudaGetSymbolAddress(&p_k,   g_k);
    cudaGetSymbolAddress(&p_vt,  g_vt);
    cudaGetSymbolAddress(&p_ctx, g_ctx);
    cudaGetSymbolAddress(&p_wt,  g_wt);
    cudaGetSymbolAddress(&p_mb,  g_mbits);

    cudaFuncSetAttribute(proj_qkv_kernel,
        cudaFuncAttributeMaxDynamicSharedMemorySize, GSMEM);
    cudaFuncSetAttribute(proj_o_kernel,
        cudaFuncAttributeMaxDynamicSharedMemorySize, GSMEM);
    cudaFuncSetAttribute(fattn_kernel,
        cudaFuncAttributeMaxDynamicSharedMemorySize, FATTN_SMEM);

    const bool fork = g_si.ok;
    cudaStream_t sm = fork ? g_si.s2 : (cudaStream_t)0;
    cudaStream_t sw = fork ? g_si.s3 : (cudaStream_t)0;

    if (fork) {
        cudaEventRecord(g_si.eFork, 0);
        cudaStreamWaitEvent(g_si.s2, g_si.eFork, 0);
        cudaStreamWaitEvent(g_si.s3, g_si.eFork, 0);
    }
    // mask branch (s2)
    detect_mask_kernel<<<1, 256, 0, sm>>>((const unsigned char*)kvm_raw,
                                          (const unsigned char*)spm_raw);
    compact_idx_kernel<<<BATCH, 256, 0, sm>>>(kvm_raw);
    if (fork) cudaEventRecord(g_si.eCompact, g_si.s2);
    mask_bits_kernel<<<BATCH * NQ, 256, 0, sm>>>(spm_raw);
    if (fork) cudaEventRecord(g_si.eMask, g_si.s2);

    // weight branch (s3)
    dim3 tb(32, 8), tg(16, 16, 4);
    wt_kernel<<<tg, tb, 0, sw>>>(Wq, Wk, Wv, Wo, (__half*)p_wt);
    if (fork) cudaEventRecord(g_si.eWt, g_si.s3);

    // main branch (default stream)
    dim3 lg(NTOK / 8, 2);
    lnorm_kernel<<<lg, 256>>>(query, key_value, ln_q_g, ln_q_b,
                              ln_kv_g, ln_kv_b,
                              (__half*)p_qn, (__half*)p_kvn);

    if (fork) {
        cudaStreamWaitEvent(0, g_si.eCompact, 0);
        cudaStreamWaitEvent(0, g_si.eWt, 0);
    }
    dim3 pg(EMB / 128, NTOK / 128, 3);
    proj_qkv_kernel<<<pg, 256, GSMEM>>>((const __half*)p_qn, (const __half*)p_kvn,
                                 (const __half*)p_wt, bq, bk, bv,
                                 (__half*)p_q, (__half*)p_k, (__half*)p_vt);

    if (fork) cudaStreamWaitEvent(0, g_si.eMask, 0);
    dim3 fg(NQ / 128, BHN);
    fattn_kernel<<<fg, 256, FATTN_SMEM>>>((const __half*)p_q, (const __half*)p_k,
                              (const __half*)p_vt,
                              (const unsigned long long*)p_mb,
                              (__half*)p_ctx);

    dim3 og(EMB / 128, NTOK / 128);
    proj_o_kernel<<<og, 256, GSMEM>>>((const __half*)p_ctx, (const __half*)p_wt,
                               bo, out);
}

// round 15
// speedup vs baseline: 1.0203x; 1.0203x over previous
#include <cuda_runtime.h>
#include <cuda_fp16.h>
#include <cstdint>
#include <cstddef>

#define BATCH 4
#define NQ    2048
#define NK    2048
#define EMB   512
#define NH    8
#define HD    64
#define NTOK  (BATCH * NQ)
#define BHN   (BATCH * NH)

// ---------------- device-global scratch ---------------------------------------
__device__ __half g_qn [NTOK * EMB];
__device__ __half g_kvn[NTOK * EMB];
__device__ __half g_q  [NTOK * EMB];          // pre-scaled by 0.125*log2(e)
__device__ __half g_k  [NTOK * EMB];          // COMPACTED rows per batch
__device__ __half g_vt [BHN * HD * NK];       // V^T per (b,h): [d][compacted key]
__device__ __half g_ctx[NTOK * EMB];
__device__ __half g_wt [4 * EMB * EMB];       // W^T, k-major rows
__device__ unsigned long long g_mbits[(size_t)BATCH * NQ * (NK / 64)];
__device__ int g_kidx[BATCH * NK];
__device__ int g_nvalid[BATCH];
__device__ int g_nkt[BATCH];
__device__ int g_is_byte[2];

// ---------------- streams/events for graph-parallel branches -------------------
struct StreamInit {
    cudaStream_t s2 = nullptr, s3 = nullptr;
    cudaEvent_t eFork = nullptr, eCompact = nullptr, eMask = nullptr, eWt = nullptr;
    bool ok = false;
    StreamInit() {
        if (cudaStreamCreateWithFlags(&s2, cudaStreamNonBlocking) != cudaSuccess) return;
        if (cudaStreamCreateWithFlags(&s3, cudaStreamNonBlocking) != cudaSuccess) return;
        if (cudaEventCreateWithFlags(&eFork, cudaEventDisableTiming) != cudaSuccess) return;
        if (cudaEventCreateWithFlags(&eCompact, cudaEventDisableTiming) != cudaSuccess) return;
        if (cudaEventCreateWithFlags(&eMask, cudaEventDisableTiming) != cudaSuccess) return;
        if (cudaEventCreateWithFlags(&eWt, cudaEventDisableTiming) != cudaSuccess) return;
        ok = true;
    }
};
static StreamInit g_si;

// ---------------- PTX helpers --------------------------------------------------
__device__ __forceinline__ uint32_t sptr(const void* p) {
    uint32_t a;
    asm("{ .reg .u64 t; cvta.to.shared.u64 t, %1; cvt.u32.u64 %0, t; }"
        : "=r"(a) : "l"(p));
    return a;
}
__device__ __forceinline__ uint32_t h2ex2(uint32_t x) {
    uint32_t r;
    asm("ex2.approx.f16x2 %0, %1;" : "=r"(r) : "r"(x));
    return r;
}

#define MMA_F16(C, A, B) \
    asm volatile( \
        "mma.sync.aligned.m16n8k16.row.col.f32.f16.f16.f32 " \
        "{%0,%1,%2,%3}, {%4,%5,%6,%7}, {%8,%9}, {%0,%1,%2,%3};" \
        : "+f"((C)[0]), "+f"((C)[1]), "+f"((C)[2]), "+f"((C)[3]) \
        : "r"((A)[0]), "r"((A)[1]), "r"((A)[2]), "r"((A)[3]), \
          "r"((B)[0]), "r"((B)[1]))

#define LDSM4(R0, R1, R2, R3, ADDR) \
    asm volatile("ldmatrix.sync.aligned.m8n8.x4.shared.b16 {%0,%1,%2,%3}, [%4];" \
        : "=r"(R0), "=r"(R1), "=r"(R2), "=r"(R3) : "r"(ADDR))

#define CP16(DST, SRC) \
    asm volatile("cp.async.cg.shared.global [%0], [%1], 16;" \
        :: "r"(DST), "l"(SRC))
#define CP_COMMIT() asm volatile("cp.async.commit_group;" ::: "memory")
#define CP_WAIT0()  asm volatile("cp.async.wait_group 0;" ::: "memory")

// ---------------- fp16 GEMM mainloop: BK=64, cp.async double-buffered ----------
#define GSMEM 73728
__device__ __forceinline__ void gemm16_mainloop(
        const __half* __restrict__ A, const int* __restrict__ ridx,
        const __half* __restrict__ B, float (&c)[2][8][4], char* sm) {
    const int tid = threadIdx.x;
    const int lane = tid & 31, wid = tid >> 5;
    const int wm = wid & 3, wn = wid >> 2;
    const uint32_t s0 = sptr(sm);

    #pragma unroll
    for (int mt = 0; mt < 2; mt++)
        #pragma unroll
        for (int nt = 0; nt < 8; nt++)
            #pragma unroll
            for (int j = 0; j < 4; j++) c[mt][nt][j] = 0.0f;

    const uint32_t a_base = s0 +
        (wm * 32 + ((lane & 8) ? 8 : 0) + (lane & 7)) * 144 + ((lane & 16) ? 16 : 0);
    const uint32_t b_base = s0 + 18432 +
        (wn * 64 + ((lane & 16) ? 8 : 0) + (lane & 7)) * 144 + ((lane & 8) ? 16 : 0);

    const int rbase = tid >> 3;
    const int fh = (tid & 7) * 8;
    const uint32_t fB = (tid & 7) * 16;
    int ar[4];
    #pragma unroll
    for (int i = 0; i < 4; i++)
        ar[i] = ridx ? ridx[rbase + 32 * i] : (rbase + 32 * i);

    #pragma unroll
    for (int i = 0; i < 4; i++) {
        int r = rbase + 32 * i;
        CP16(s0 + r * 144 + fB, A + (size_t)ar[i] * EMB + fh);
        CP16(s0 + 18432 + r * 144 + fB, B + (size_t)r * EMB + fh);
    }
    CP_COMMIT();

    for (int ch = 0; ch < 8; ch++) {
        const int buf = ch & 1;
        CP_WAIT0();
        __syncthreads();
        if (ch + 1 < 8) {
            const uint32_t nb = (uint32_t)((ch + 1) & 1) * 36864u;
            const int co = (ch + 1) * 64 + fh;
            #pragma unroll
            for (int i = 0; i < 4; i++) {
                int r = rbase + 32 * i;
                CP16(s0 + nb + r * 144 + fB, A + (size_t)ar[i] * EMB + co);
                CP16(s0 + nb + 18432 + r * 144 + fB, B + (size_t)r * EMB + co);
            }
            CP_COMMIT();
        }
        const uint32_t ab = a_base + buf * 36864u;
        const uint32_t bb = b_base + buf * 36864u;
        #pragma unroll
        for (int ks = 0; ks < 4; ks++) {
            uint32_t a[2][4], b[8][2];
            #pragma unroll
            for (int mt = 0; mt < 2; mt++)
                LDSM4(a[mt][0], a[mt][1], a[mt][2], a[mt][3],
                      ab + mt * 16 * 144 + ks * 32);
            #pragma unroll
            for (int p = 0; p < 4; p++)
                LDSM4(b[2*p][0], b[2*p][1], b[2*p+1][0], b[2*p+1][1],
                      bb + p * 16 * 144 + ks * 32);
            #pragma unroll
            for (int mt = 0; mt < 2; mt++)
                #pragma unroll
                for (int nt = 0; nt < 8; nt++)
                    MMA_F16(c[mt][nt], a[mt], b[nt]);
        }
    }
}

// Q/K/V projections. z=0: Q (scaled 0.125*log2e), z=1: K (gathered), z=2: V^T.
__global__ void __launch_bounds__(256, 2) proj_qkv_kernel(
        const __half* __restrict__ qn, const __half* __restrict__ kvn,
        const __half* __restrict__ wt,
        const float* __restrict__ bq, const float* __restrict__ bk,
        const float* __restrict__ bv,
        __half* __restrict__ q, __half* __restrict__ k,
        __half* __restrict__ vt) {
    extern __shared__ __align__(16) char smqkv[];
    const int z = blockIdx.z;
    const size_t bm = (size_t)blockIdx.y * 128, bn = (size_t)blockIdx.x * 128;
    const int bb = (int)(bm >> 11);
    const int rloc = (int)(bm & 2047);

    const int* ridx = nullptr;
    const __half* A;
    if (z == 0) {
        A = qn + bm * EMB;
    } else {
        if (rloc >= g_nkt[bb] * 64) return;
        A = kvn + (size_t)bb * 2048 * EMB;
        ridx = g_kidx + bb * NK + rloc;
    }
    const __half* B = wt + (size_t)z * EMB * EMB + bn * EMB;
    float c[2][8][4];
    gemm16_mainloop(A, ridx, B, c, smqkv);

    const int tid = threadIdx.x, lane = tid & 31, wid = tid >> 5;
    const int wm = wid & 3, wn = wid >> 2, g = lane >> 2, t = lane & 3;
    const float* bias = (z == 0) ? bq : (z == 1) ? bk : bv;
    const float scale = (z == 0) ? 0.1803368801111244f : 1.0f;  // 0.125*log2(e)

    if (z < 2) {
        #pragma unroll
        for (int mt = 0; mt < 2; mt++) {
            #pragma unroll
            for (int nt = 0; nt < 8; nt++) {
                int m   = (int)bm + wm * 32 + mt * 16 + g;
                int col = (int)bn + wn * 64 + nt * 8 + 2 * t;
                float b0 = bias[col], b1 = bias[col + 1];
                float v0 = (c[mt][nt][0] + b0) * scale;
                float v1 = (c[mt][nt][1] + b1) * scale;
                float v2 = (c[mt][nt][2] + b0) * scale;
                float v3 = (c[mt][nt][3] + b1) * scale;
                __half* dst = (z == 0) ? q : k;
                *(half2*)(dst + (size_t)m * EMB + col) = __floats2half2_rn(v0, v1);
                *(half2*)(dst + (size_t)(m + 8) * EMB + col) = __floats2half2_rn(v2, v3);
            }
        }
    } else {
        __half* smT = (__half*)smqkv;
        __syncthreads();
        #pragma unroll
        for (int mt = 0; mt < 2; mt++) {
            #pragma unroll
            for (int nt = 0; nt < 8; nt++) {
                int m   = wm * 32 + mt * 16 + g;
                int col = wn * 64 + nt * 8 + 2 * t;
                float b0 = bias[(int)bn + col], b1 = bias[(int)bn + col + 1];
                smT[col * 136 + m]           = __float2half_rn(c[mt][nt][0] + b0);
                smT[(col + 1) * 136 + m]     = __float2half_rn(c[mt][nt][1] + b1);
                smT[col * 136 + m + 8]       = __float2half_rn(c[mt][nt][2] + b0);
                smT[(col + 1) * 136 + m + 8] = __float2half_rn(c[mt][nt][3] + b1);
            }
        }
        __syncthreads();
        int col = tid >> 1;
        int mo  = (tid & 1) * 64;
        int gc  = (int)bn + col;
        int h = gc >> 6, d = gc & 63;
        size_t orow = ((size_t)(bb * NH + h) * HD + d) * NK + (size_t)rloc + mo;
        const uint4* srcp = (const uint4*)(smT + col * 136 + mo);
        uint4* dstp = (uint4*)(vt + orow);
        #pragma unroll
        for (int j = 0; j < 8; j++) dstp[j] = srcp[j];
    }
}

__global__ void __launch_bounds__(256, 2) proj_o_kernel(
        const __half* __restrict__ ctx, const __half* __restrict__ wt,
        const float* __restrict__ bo, float* __restrict__ out) {
    extern __shared__ __align__(16) char smo[];
    const size_t bm = (size_t)blockIdx.y * 128, bn = (size_t)blockIdx.x * 128;
    float c[2][8][4];
    gemm16_mainloop(ctx + bm * EMB, nullptr,
                    wt + 3ull * EMB * EMB + bn * EMB, c, smo);

    const int tid = threadIdx.x, lane = tid & 31, wid = tid >> 5;
    const int wm = wid & 3, wn = wid >> 2, g = lane >> 2, t = lane & 3;
    #pragma unroll
    for (int mt = 0; mt < 2; mt++) {
        #pragma unroll
        for (int nt = 0; nt < 8; nt++) {
            int m   = (int)bm + wm * 32 + mt * 16 + g;
            int col = (int)bn + wn * 64 + nt * 8 + 2 * t;
            float b0 = bo[col], b1 = bo[col + 1];
            *(float2*)(out + (size_t)m * EMB + col) =
                make_float2(c[mt][nt][0] + b0, c[mt][nt][1] + b1);
            *(float2*)(out + (size_t)(m + 8) * EMB + col) =
                make_float2(c[mt][nt][2] + b0, c[mt][nt][3] + b1);
        }
    }
}

// ---------------- fused flash attention (R13 base + mask-after-max) -------------
// Dynamic smem (halves): Ks 2x[64][72] at 0 (buf stride 9216B);
// Vst 2x[80][72] at 9216h (buf stride 11520B; rows 64..79 = ones/zeros).
#define FATTN_SMEM 41472
__global__ void __launch_bounds__(256, 2) fattn_kernel(
        const __half* __restrict__ Qp, const __half* __restrict__ Kp,
        const __half* __restrict__ Vtp,
        const unsigned long long* __restrict__ mbits,
        __half* __restrict__ ctx) {
    extern __shared__ __align__(16) __half smd[];
    __half* KsB = smd;
    __half* VsB = smd + 9216;

    const int tid = threadIdx.x;
    const int lane = tid & 31, w = tid >> 5;
    const int g = lane >> 2, t = lane & 3;
    const int qt = blockIdx.x, bh = blockIdx.y;
    const int b = bh >> 3, h = bh & 7;
    const int row0 = w * 16 + g, row1 = row0 + 8;
    const int nkt = g_nkt[b];

    const uint32_t ks_smem = sptr(KsB);
    const uint32_t vs_smem = sptr(VsB);
    const uint32_t lrow = ((lane & 16) ? 8 : 0) + (lane & 7);
    const uint32_t k_base = ks_smem + lrow * 144 + ((lane & 8) ? 16 : 0);
    const uint32_t v_base = vs_smem + lrow * 144 + ((lane & 8) ? 16 : 0);

    // ones/zeros rows 64..79 of both V buffers (row 64 = 1, rest 0)
    for (int idx = tid; idx < 2 * 16 * 72; idx += 256) {
        int bufr = idx / 72, col = idx % 72;
        int buf = bufr >> 4, row = 64 + (bufr & 15);
        VsB[buf * 5760 + row * 72 + col] =
            (row == 64) ? __float2half(1.0f) : __float2half(0.0f);
    }

    uint32_t qa[4][4];
    {
        const __half* q0 = Qp + (size_t)(b * NQ + qt * 128 + row0) * EMB + h * HD;
        const __half* q1 = Qp + (size_t)(b * NQ + qt * 128 + row1) * EMB + h * HD;
        #pragma unroll
        for (int ks = 0; ks < 4; ks++) {
            qa[ks][0] = *(const uint32_t*)(q0 + ks * 16 + 2 * t);
            qa[ks][1] = *(const uint32_t*)(q1 + ks * 16 + 2 * t);
            qa[ks][2] = *(const uint32_t*)(q0 + ks * 16 + 2 * t + 8);
            qa[ks][3] = *(const uint32_t*)(q1 + ks * 16 + 2 * t + 8);
        }
    }

    float m0 = -40.0f, m1 = -40.0f;          // log2-domain running max
    float acc[9][4];
    #pragma unroll
    for (int nt = 0; nt < 9; nt++)
        #pragma unroll
        for (int j = 0; j < 4; j++) acc[nt][j] = 0.0f;

    const unsigned long long* mb0 =
        mbits + ((size_t)b * NQ + qt * 128 + row0) * (NK / 64);
    const unsigned long long* mb1 =
        mbits + ((size_t)b * NQ + qt * 128 + row1) * (NK / 64);

    const __half* Kbase  = Kp + ((size_t)b * NK) * EMB + h * HD;
    const __half* Vtbase = Vtp + (size_t)bh * HD * NK;

    if (nkt > 0) {
        #pragma unroll
        for (int i = 0; i < 2; i++) {
            int s = tid + i * 256;
            int r = s >> 3, f = s & 7;
            CP16(ks_smem + r * 144 + f * 16, Kbase + (size_t)r * EMB + f * 8);
            CP16(vs_smem + r * 144 + f * 16, Vtbase + (size_t)r * NK + f * 8);
        }
        CP_COMMIT();
    }

    for (int kt = 0; kt < nkt; kt++) {
        const int buf = kt & 1;
        unsigned long long w0 = mb0[kt], w1 = mb1[kt];

        // build AND-masks early (off the critical chain, overlaps staging + MMAs)
        uint32_t um[4][4];
        #pragma unroll
        for (int ks = 0; ks < 4; ks++) {
            int cA = ks * 16 + 2 * t;
            int cB = cA + 8;
            uint32_t a0 = (uint32_t)(w0 >> cA) & 3u;
            uint32_t a1 = (uint32_t)(w1 >> cA) & 3u;
            uint32_t b0 = (uint32_t)(w0 >> cB) & 3u;
            uint32_t b1 = (uint32_t)(w1 >> cB) & 3u;
            um[ks][0] = ((a0 & 1u) * 0xFFFFu) | ((a0 >> 1) * 0xFFFF0000u);
            um[ks][1] = ((a1 & 1u) * 0xFFFFu) | ((a1 >> 1) * 0xFFFF0000u);
            um[ks][2] = ((b0 & 1u) * 0xFFFFu) | ((b0 >> 1) * 0xFFFF0000u);
            um[ks][3] = ((b1 & 1u) * 0xFFFFu) | ((b1 >> 1) * 0xFFFF0000u);
        }

        CP_WAIT0();
        __syncthreads();

        if (kt + 1 < nkt) {
            int k0n = (kt + 1) * 64;
            int nbuf = buf ^ 1;
            #pragma unroll
            for (int i = 0; i < 2; i++) {
                int s = tid + i * 256;
                int r = s >> 3, f = s & 7;
                CP16(ks_smem + nbuf * 9216 + r * 144 + f * 16,
                     Kbase + (size_t)(k0n + r) * EMB + f * 8);
                CP16(vs_smem + nbuf * 11520 + r * 144 + f * 16,
                     Vtbase + (size_t)r * NK + k0n + f * 8);
            }
            CP_COMMIT();
        }

        // S = Q @ K^T (log2 units)
        float sc[8][4];
        #pragma unroll
        for (int nt = 0; nt < 8; nt++)
            #pragma unroll
            for (int j = 0; j < 4; j++) sc[nt][j] = 0.0f;
        const uint32_t kb = k_base + buf * 9216;
        #pragma unroll
        for (int ks = 0; ks < 4; ks++) {
            uint32_t bf[8][2];
            #pragma unroll
            for (int p = 0; p < 4; p++)
                LDSM4(bf[2*p][0], bf[2*p][1], bf[2*p+1][0], bf[2*p+1][1],
                      kb + p * 16 * 144 + ks * 32);
            #pragma unroll
            for (int nt = 0; nt < 8; nt++)
                MMA_F16(sc[nt], qa[ks], bf[nt]);
        }

        // tile max over RAW scores (mask applied later via AND; m is a valid
        // per-row upper bound and cancels exactly in O/l)
        float tm0 = -1e30f, tm1 = -1e30f;
        #pragma unroll
        for (int nt = 0; nt < 8; nt++) {
            tm0 = fmaxf(tm0, fmaxf(sc[nt][0], sc[nt][1]));
            tm1 = fmaxf(tm1, fmaxf(sc[nt][2], sc[nt][3]));
        }
        tm0 = fmaxf(tm0, __shfl_xor_sync(0xffffffffu, tm0, 1));
        tm0 = fmaxf(tm0, __shfl_xor_sync(0xffffffffu, tm0, 2));
        tm1 = fmaxf(tm1, __shfl_xor_sync(0xffffffffu, tm1, 1));
        tm1 = fmaxf(tm1, __shfl_xor_sync(0xffffffffu, tm1, 2));

        float mn0 = fmaxf(m0, tm0), mn1 = fmaxf(m1, tm1);
        if (__any_sync(0xffffffffu, (mn0 > m0) | (mn1 > m1))) {
            float corr0 = exp2f(m0 - mn0);
            float corr1 = exp2f(m1 - mn1);
            #pragma unroll
            for (int nt = 0; nt < 9; nt++) {
                acc[nt][0] *= corr0; acc[nt][1] *= corr0;
                acc[nt][2] *= corr1; acc[nt][3] *= corr1;
            }
            m0 = mn0;  m1 = mn1;
        }

        // P in registers (FA-2 layout identity), masked via AND
        uint32_t pfrag[4][4];
        #pragma unroll
        for (int ks = 0; ks < 4; ks++) {
            half2 h00 = __floats2half2_rn(sc[2*ks][0] - m0, sc[2*ks][1] - m0);
            half2 h01 = __floats2half2_rn(sc[2*ks][2] - m1, sc[2*ks][3] - m1);
            half2 h10 = __floats2half2_rn(sc[2*ks+1][0] - m0, sc[2*ks+1][1] - m0);
            half2 h11 = __floats2half2_rn(sc[2*ks+1][2] - m1, sc[2*ks+1][3] - m1);
            pfrag[ks][0] = h2ex2(*(uint32_t*)&h00) & um[ks][0];
            pfrag[ks][1] = h2ex2(*(uint32_t*)&h01) & um[ks][1];
            pfrag[ks][2] = h2ex2(*(uint32_t*)&h10) & um[ks][2];
            pfrag[ks][3] = h2ex2(*(uint32_t*)&h11) & um[ks][3];
        }

        // O += P @ V  (tile nt=8 is the ones-column -> running row sum l)
        const uint32_t vb = v_base + buf * 11520;
        #pragma unroll
        for (int ks = 0; ks < 4; ks++) {
            uint32_t bv[10][2];
            #pragma unroll
            for (int p = 0; p < 5; p++)
                LDSM4(bv[2*p][0], bv[2*p][1], bv[2*p+1][0], bv[2*p+1][1],
                      vb + p * 16 * 144 + ks * 32);
            #pragma unroll
            for (int nt = 0; nt < 9; nt++)
                MMA_F16(acc[nt], pfrag[ks], bv[nt]);
        }
    }

    float l0 = __shfl_sync(0xffffffffu, acc[8][0], lane & 28);
    float l1 = __shfl_sync(0xffffffffu, acc[8][2], lane & 28);
    float inv0 = (l0 > 0.0f) ? (1.0f / l0) : 0.0f;
    float inv1 = (l1 > 0.0f) ? (1.0f / l1) : 0.0f;
    __half* o0 = ctx + (size_t)(b * NQ + qt * 128 + row0) * EMB + h * HD;
    __half* o1 = ctx + (size_t)(b * NQ + qt * 128 + row1) * EMB + h * HD;
    #pragma unroll
    for (int nt = 0; nt < 8; nt++) {
        int c0 = nt * 8 + 2 * t;
        *(half2*)(o0 + c0) = __floats2half2_rn(acc[nt][0] * inv0, acc[nt][1] * inv0);
        *(half2*)(o1 + c0) = __floats2half2_rn(acc[nt][2] * inv1, acc[nt][3] * inv1);
    }
}

// ---------------- mask dtype sniff ---------------------------------------------
__global__ void detect_mask_kernel(const unsigned char* kvm_raw,
                                   const unsigned char* spm_raw) {
    __shared__ int found[2];
    if (threadIdx.x == 0) { found[0] = 0; found[1] = 0; }
    __syncthreads();
    for (int i = threadIdx.x; i < 8192; i += blockDim.x) {
        if ((i & 3) != 0) {
            if (kvm_raw[i]) atomicOr(&found[0], 1);
            if (spm_raw[i]) atomicOr(&found[1], 1);
        }
    }
    __syncthreads();
    if (threadIdx.x == 0) { g_is_byte[0] = found[0]; g_is_byte[1] = found[1]; }
}

// ---------------- kv_mask stream compaction -------------------------------------
__global__ void compact_idx_kernel(const void* kvm_raw) {
    const int b = blockIdx.x;
    const int tid = threadIdx.x;
    const int lane = tid & 31, w = tid >> 5;
    __shared__ int base;
    __shared__ int wstart[8];
    __shared__ int wcnt[8];
    if (tid == 0) base = 0;
    __syncthreads();
    const bool kb = g_is_byte[0] != 0;
    for (int c0 = 0; c0 < NK; c0 += 256) {
        int kk = c0 + tid;
        bool v = kb ? (((const unsigned char*)kvm_raw)[b * NK + kk] != 0)
                    : (((const int*)kvm_raw)[b * NK + kk] != 0);
        unsigned bal = __ballot_sync(0xffffffffu, v);
        if (lane == 0) wcnt[w] = __popc(bal);
        __syncthreads();
        if (tid == 0) {
            int s = base;
            #pragma unroll
            for (int i = 0; i < 8; i++) { wstart[i] = s; s += wcnt[i]; }
            base = s;
        }
        __syncthreads();
        if (v)
            g_kidx[b * NK + wstart[w] + __popc(bal & ((1u << lane) - 1))] = kk;
        __syncthreads();
    }
    int nv = base;
    for (int c = nv + tid; c < NK; c += 256) g_kidx[b * NK + c] = 0;
    if (tid == 0) {
        g_nvalid[b] = nv;
        g_nkt[b] = (nv + 63) >> 6;
    }
}

// ---------------- sparse-mask bits (coalesced via smem) --------------------------
__global__ void __launch_bounds__(256) mask_bits_kernel(const void* spm_raw) {
    __shared__ unsigned char sp_sm[2048];
    __shared__ uint32_t wb[64];
    const int bq = blockIdx.x;
    const int b = bq >> 11;
    const int tid = threadIdx.x;

    if (g_is_byte[1]) {
        const uint32_t* sp = (const uint32_t*)
            ((const unsigned char*)spm_raw + (size_t)bq * NK);
        for (int i = tid; i < 512; i += 256) {
            uint32_t v = sp[i];
            sp_sm[i * 4 + 0] = (v & 0x000000ffu) ? 1 : 0;
            sp_sm[i * 4 + 1] = (v & 0x0000ff00u) ? 1 : 0;
            sp_sm[i * 4 + 2] = (v & 0x00ff0000u) ? 1 : 0;
            sp_sm[i * 4 + 3] = (v & 0xff000000u) ? 1 : 0;
        }
    } else {
        const int* sp = (const int*)spm_raw + (size_t)bq * NK;
        for (int i = tid; i < 2048; i += 256)
            sp_sm[i] = sp[i] ? 1 : 0;
    }
    __syncthreads();

    const int nv = g_nvalid[b];
    const int* kidx = g_kidx + b * NK;
    #pragma unroll
    for (int i = 0; i < 8; i++) {
        int c = i * 256 + tid;
        bool bit = (c < nv) && (sp_sm[kidx[c]] != 0);
        unsigned bal = __ballot_sync(0xffffffffu, bit);
        if ((tid & 31) == 0) wb[i * 8 + (tid >> 5)] = bal;
    }
    __syncthreads();
    if (tid < 32) {
        int i = tid >> 2, wp = (tid & 3) * 2;
        uint64_t wv = (uint64_t)wb[i * 8 + wp] |
                      ((uint64_t)wb[i * 8 + wp + 1] << 32);
        g_mbits[(size_t)bq * 32 + tid] = wv;
    }
}

// ---------------- LayerNorm (warp-per-row, shuffle-only) ------------------------
__global__ void __launch_bounds__(256) lnorm_kernel(
        const float* __restrict__ xq, const float* __restrict__ xkv,
        const float* __restrict__ gq, const float* __restrict__ bq,
        const float* __restrict__ gkv, const float* __restrict__ bkv,
        __half* __restrict__ yq, __half* __restrict__ ykv) {
    const int row = blockIdx.x * 8 + (threadIdx.x >> 5);
    const int lane = threadIdx.x & 31;
    const float* x = blockIdx.y ? xkv : xq;
    const float* g = blockIdx.y ? gkv : gq;
    const float* b = blockIdx.y ? bkv : bq;
    __half* y      = blockIdx.y ? ykv : yq;

    const float4* xr = (const float4*)(x + (size_t)row * EMB);
    float4 v[4];
    float s = 0.0f, s2 = 0.0f;
    #pragma unroll
    for (int j = 0; j < 4; j++) {
        v[j] = xr[lane + 32 * j];
        s  += v[j].x + v[j].y + v[j].z + v[j].w;
        s2 += v[j].x*v[j].x + v[j].y*v[j].y + v[j].z*v[j].z + v[j].w*v[j].w;
    }
    #pragma unroll
    for (int o = 16; o > 0; o >>= 1) {
        s  += __shfl_xor_sync(0xffffffffu, s,  o);
        s2 += __shfl_xor_sync(0xffffffffu, s2, o);
    }
    float mu  = s * (1.0f / EMB);
    float var = s2 * (1.0f / EMB) - mu * mu;
    float inv = rsqrtf(var + 1e-5f);
    #pragma unroll
    for (int j = 0; j < 4; j++) {
        float4 gg = ((const float4*)g)[lane + 32 * j];
        float4 bb = ((const float4*)b)[lane + 32 * j];
        half2 h0 = __floats2half2_rn((v[j].x - mu) * inv * gg.x + bb.x,
                                     (v[j].y - mu) * inv * gg.y + bb.y);
        half2 h1 = __floats2half2_rn((v[j].z - mu) * inv * gg.z + bb.z,
                                     (v[j].w - mu) * inv * gg.w + bb.w);
        uint2 o2 = make_uint2(*(uint32_t*)&h0, *(uint32_t*)&h1);
        *(uint2*)(y + (size_t)row * EMB + (lane + 32 * j) * 4) = o2;
    }
}

// ---------------- weight transpose ------------------------------------------------
__global__ void wt_kernel(const float* __restrict__ Wq,
                          const float* __restrict__ Wk,
                          const float* __restrict__ Wv,
                          const float* __restrict__ Wo,
                          __half* __restrict__ Wt) {
    __shared__ float tile[32][33];
    int z = blockIdx.z;
    const float* W = (z == 0) ? Wq : (z == 1) ? Wk : (z == 2) ? Wv : Wo;
    __half* dst = Wt + (size_t)z * EMB * EMB;
    int bx = blockIdx.x * 32, by = blockIdx.y * 32;
    int tx = threadIdx.x, ty = threadIdx.y;
    #pragma unroll
    for (int i = 0; i < 4; i++)
        tile[ty + i * 8][tx] = W[(size_t)(by + ty + i * 8) * EMB + bx + tx];
    __syncthreads();
    #pragma unroll
    for (int i = 0; i < 4; i++)
        dst[(size_t)(bx + ty + i * 8) * EMB + by + tx] =
            __float2half_rn(tile[tx][ty + i * 8]);
}

// ---------------- launch ----------------------------------------------------------
extern "C" void kernel_launch(void* const* d_in, const int* in_sizes, int n_in,
                              void* d_out, int out_size) {
    const float* query     = (const float*)d_in[0];
    const float* key_value = (const float*)d_in[1];
    const void*  kvm_raw   = d_in[2];
    const void*  spm_raw   = d_in[3];
    const float* ln_q_g  = (const float*)d_in[4];
    const float* ln_q_b  = (const float*)d_in[5];
    const float* ln_kv_g = (const float*)d_in[6];
    const float* ln_kv_b = (const float*)d_in[7];
    const float* Wq = (const float*)d_in[8];
    const float* bq = (const float*)d_in[9];
    const float* Wk = (const float*)d_in[10];
    const float* bk = (const float*)d_in[11];
    const float* Wv = (const float*)d_in[12];
    const float* bv = (const float*)d_in[13];
    const float* Wo = (const float*)d_in[14];
    const float* bo = (const float*)d_in[15];
    float* out = (float*)d_out;

    void *p_qn, *p_kvn, *p_q, *p_k, *p_vt, *p_ctx, *p_wt, *p_mb;
    cudaGetSymbolAddress(&p_qn,  g_qn);
    cudaGetSymbolAddress(&p_kvn, g_kvn);
    cudaGetSymbolAddress(&p_q,   g_q);
    cudaGetSymbolAddress(&p_k,   g_k);
    cudaGetSymbolAddress(&p_vt,  g_vt);
    cudaGetSymbolAddress(&p_ctx, g_ctx);
    cudaGetSymbolAddress(&p_wt,  g_wt);
    cudaGetSymbolAddress(&p_mb,  g_mbits);

    cudaFuncSetAttribute(proj_qkv_kernel,
        cudaFuncAttributeMaxDynamicSharedMemorySize, GSMEM);
    cudaFuncSetAttribute(proj_o_kernel,
        cudaFuncAttributeMaxDynamicSharedMemorySize, GSMEM);
    cudaFuncSetAttribute(fattn_kernel,
        cudaFuncAttributeMaxDynamicSharedMemorySize, FATTN_SMEM);

    const bool fork = g_si.ok;
    cudaStream_t sm = fork ? g_si.s2 : (cudaStream_t)0;
    cudaStream_t sw = fork ? g_si.s3 : (cudaStream_t)0;

    if (fork) {
        cudaEventRecord(g_si.eFork, 0);
        cudaStreamWaitEvent(g_si.s2, g_si.eFork, 0);
        cudaStreamWaitEvent(g_si.s3, g_si.eFork, 0);
    }
    // mask branch (s2)
    detect_mask_kernel<<<1, 256, 0, sm>>>((const unsigned char*)kvm_raw,
                                          (const unsigned char*)spm_raw);
    compact_idx_kernel<<<BATCH, 256, 0, sm>>>(kvm_raw);
    if (fork) cudaEventRecord(g_si.eCompact, g_si.s2);
    mask_bits_kernel<<<BATCH * NQ, 256, 0, sm>>>(spm_raw);
    if (fork) cudaEventRecord(g_si.eMask, g_si.s2);

    // weight branch (s3)
    dim3 tb(32, 8), tg(16, 16, 4);
    wt_kernel<<<tg, tb, 0, sw>>>(Wq, Wk, Wv, Wo, (__half*)p_wt);
    if (fork) cudaEventRecord(g_si.eWt, g_si.s3);

    // main branch (default stream)
    dim3 lg(NTOK / 8, 2);
    lnorm_kernel<<<lg, 256>>>(query, key_value, ln_q_g, ln_q_b,
                              ln_kv_g, ln_kv_b,
                              (__half*)p_qn, (__half*)p_kvn);

    if (fork) {
        cudaStreamWaitEvent(0, g_si.eCompact, 0);
        cudaStreamWaitEvent(0, g_si.eWt, 0);
    }
    dim3 pg(EMB / 128, NTOK / 128, 3);
    proj_qkv_kernel<<<pg, 256, GSMEM>>>((const __half*)p_qn, (const __half*)p_kvn,
                                 (const __half*)p_wt, bq, bk, bv,
                                 (__half*)p_q, (__half*)p_k, (__half*)p_vt);

    if (fork) cudaStreamWaitEvent(0, g_si.eMask, 0);
    dim3 fg(NQ / 128, BHN);
    fattn_kernel<<<fg, 256, FATTN_SMEM>>>((const __half*)p_q, (const __half*)p_k,
                              (const __half*)p_vt,
                              (const unsigned long long*)p_mb,
                              (__half*)p_ctx);

    dim3 og(EMB / 128, NTOK / 128);
    proj_o_kernel<<<og, 256, GSMEM>>>((const __half*)p_ctx, (const __half*)p_wt,
                               bo, out);
}

// round 16
// speedup vs baseline: 1.0817x; 1.0602x over previous
#include <cuda_runtime.h>
#include <cuda_fp16.h>
#include <cstdint>
#include <cstddef>

#define BATCH 4
#define NQ    2048
#define NK    2048
#define EMB   512
#define NH    8
#define HD    64
#define NTOK  (BATCH * NQ)
#define BHN   (BATCH * NH)

// ---------------- device-global scratch ---------------------------------------
__device__ __half g_qn [NTOK * EMB];
__device__ __half g_kvn[NTOK * EMB];
__device__ __half g_q  [NTOK * EMB];          // pre-scaled by 0.125*log2(e)
__device__ __half g_k  [NTOK * EMB];          // COMPACTED rows per batch
__device__ __half g_vt [BHN * HD * NK];       // V^T per (b,h): [d][compacted key]
__device__ __half g_ctx[NTOK * EMB];
__device__ __half g_wt [4 * EMB * EMB];       // W^T, k-major rows
__device__ unsigned long long g_mbits[(size_t)BATCH * NQ * (NK / 64)];
__device__ int g_kidx[BATCH * NK];
__device__ int g_nvalid[BATCH];
__device__ int g_nkt[BATCH];
__device__ int g_is_byte[2];

// ---------------- streams/events for batch-pipelined graph ---------------------
struct StreamInit {
    cudaStream_t s2 = nullptr, s3 = nullptr, sb[4] = {nullptr, nullptr, nullptr, nullptr};
    cudaEvent_t eFork = nullptr, eCompact = nullptr, eWt = nullptr;
    cudaEvent_t eMaskB[4] = {}, eDone[3] = {};
    bool ok = false;
    StreamInit() {
        if (cudaStreamCreateWithFlags(&s2, cudaStreamNonBlocking) != cudaSuccess) return;
        if (cudaStreamCreateWithFlags(&s3, cudaStreamNonBlocking) != cudaSuccess) return;
        sb[0] = nullptr;  // batch 0 uses default stream
        for (int i = 1; i < 4; i++)
            if (cudaStreamCreateWithFlags(&sb[i], cudaStreamNonBlocking) != cudaSuccess) return;
        if (cudaEventCreateWithFlags(&eFork, cudaEventDisableTiming) != cudaSuccess) return;
        if (cudaEventCreateWithFlags(&eCompact, cudaEventDisableTiming) != cudaSuccess) return;
        if (cudaEventCreateWithFlags(&eWt, cudaEventDisableTiming) != cudaSuccess) return;
        for (int i = 0; i < 4; i++)
            if (cudaEventCreateWithFlags(&eMaskB[i], cudaEventDisableTiming) != cudaSuccess) return;
        for (int i = 0; i < 3; i++)
            if (cudaEventCreateWithFlags(&eDone[i], cudaEventDisableTiming) != cudaSuccess) return;
        ok = true;
    }
};
static StreamInit g_si;

// ---------------- PTX helpers --------------------------------------------------
__device__ __forceinline__ uint32_t sptr(const void* p) {
    uint32_t a;
    asm("{ .reg .u64 t; cvta.to.shared.u64 t, %1; cvt.u32.u64 %0, t; }"
        : "=r"(a) : "l"(p));
    return a;
}
__device__ __forceinline__ uint32_t h2ex2(uint32_t x) {
    uint32_t r;
    asm("ex2.approx.f16x2 %0, %1;" : "=r"(r) : "r"(x));
    return r;
}

#define MMA_F16(C, A, B) \
    asm volatile( \
        "mma.sync.aligned.m16n8k16.row.col.f32.f16.f16.f32 " \
        "{%0,%1,%2,%3}, {%4,%5,%6,%7}, {%8,%9}, {%0,%1,%2,%3};" \
        : "+f"((C)[0]), "+f"((C)[1]), "+f"((C)[2]), "+f"((C)[3]) \
        : "r"((A)[0]), "r"((A)[1]), "r"((A)[2]), "r"((A)[3]), \
          "r"((B)[0]), "r"((B)[1]))

#define LDSM4(R0, R1, R2, R3, ADDR) \
    asm volatile("ldmatrix.sync.aligned.m8n8.x4.shared.b16 {%0,%1,%2,%3}, [%4];" \
        : "=r"(R0), "=r"(R1), "=r"(R2), "=r"(R3) : "r"(ADDR))

#define CP16(DST, SRC) \
    asm volatile("cp.async.cg.shared.global [%0], [%1], 16;" \
        :: "r"(DST), "l"(SRC))
#define CP_COMMIT() asm volatile("cp.async.commit_group;" ::: "memory")
#define CP_WAIT0()  asm volatile("cp.async.wait_group 0;" ::: "memory")

// ---------------- fp16 GEMM mainloop: BK=64, cp.async double-buffered ----------
#define GSMEM 73728
__device__ __forceinline__ void gemm16_mainloop(
        const __half* __restrict__ A, const int* __restrict__ ridx,
        const __half* __restrict__ B, float (&c)[2][8][4], char* sm) {
    const int tid = threadIdx.x;
    const int lane = tid & 31, wid = tid >> 5;
    const int wm = wid & 3, wn = wid >> 2;
    const uint32_t s0 = sptr(sm);

    #pragma unroll
    for (int mt = 0; mt < 2; mt++)
        #pragma unroll
        for (int nt = 0; nt < 8; nt++)
            #pragma unroll
            for (int j = 0; j < 4; j++) c[mt][nt][j] = 0.0f;

    const uint32_t a_base = s0 +
        (wm * 32 + ((lane & 8) ? 8 : 0) + (lane & 7)) * 144 + ((lane & 16) ? 16 : 0);
    const uint32_t b_base = s0 + 18432 +
        (wn * 64 + ((lane & 16) ? 8 : 0) + (lane & 7)) * 144 + ((lane & 8) ? 16 : 0);

    const int rbase = tid >> 3;
    const int fh = (tid & 7) * 8;
    const uint32_t fB = (tid & 7) * 16;
    int ar[4];
    #pragma unroll
    for (int i = 0; i < 4; i++)
        ar[i] = ridx ? ridx[rbase + 32 * i] : (rbase + 32 * i);

    #pragma unroll
    for (int i = 0; i < 4; i++) {
        int r = rbase + 32 * i;
        CP16(s0 + r * 144 + fB, A + (size_t)ar[i] * EMB + fh);
        CP16(s0 + 18432 + r * 144 + fB, B + (size_t)r * EMB + fh);
    }
    CP_COMMIT();

    for (int ch = 0; ch < 8; ch++) {
        const int buf = ch & 1;
        CP_WAIT0();
        __syncthreads();
        if (ch + 1 < 8) {
            const uint32_t nb = (uint32_t)((ch + 1) & 1) * 36864u;
            const int co = (ch + 1) * 64 + fh;
            #pragma unroll
            for (int i = 0; i < 4; i++) {
                int r = rbase + 32 * i;
                CP16(s0 + nb + r * 144 + fB, A + (size_t)ar[i] * EMB + co);
                CP16(s0 + nb + 18432 + r * 144 + fB, B + (size_t)r * EMB + co);
            }
            CP_COMMIT();
        }
        const uint32_t ab = a_base + buf * 36864u;
        const uint32_t bb = b_base + buf * 36864u;
        #pragma unroll
        for (int ks = 0; ks < 4; ks++) {
            uint32_t a[2][4], b[8][2];
            #pragma unroll
            for (int mt = 0; mt < 2; mt++)
                LDSM4(a[mt][0], a[mt][1], a[mt][2], a[mt][3],
                      ab + mt * 16 * 144 + ks * 32);
            #pragma unroll
            for (int p = 0; p < 4; p++)
                LDSM4(b[2*p][0], b[2*p][1], b[2*p+1][0], b[2*p+1][1],
                      bb + p * 16 * 144 + ks * 32);
            #pragma unroll
            for (int mt = 0; mt < 2; mt++)
                #pragma unroll
                for (int nt = 0; nt < 8; nt++)
                    MMA_F16(c[mt][nt], a[mt], b[nt]);
        }
    }
}

// Q/K/V projections for ONE batch. z=0: Q (scaled), z=1: K, z=2: V^T.
__global__ void __launch_bounds__(256, 2) proj_qkv_kernel(
        int b0,
        const __half* __restrict__ qn, const __half* __restrict__ kvn,
        const __half* __restrict__ wt,
        const float* __restrict__ bq, const float* __restrict__ bk,
        const float* __restrict__ bv,
        __half* __restrict__ q, __half* __restrict__ k,
        __half* __restrict__ vt) {
    extern __shared__ __align__(16) char smqkv[];
    const int z = blockIdx.z;
    const int rloc = blockIdx.y * 128;
    const size_t bm = (size_t)b0 * NQ + rloc;
    const size_t bn = (size_t)blockIdx.x * 128;

    const int* ridx = nullptr;
    const __half* A;
    if (z == 0) {
        A = qn + bm * EMB;
    } else {
        if (rloc >= g_nkt[b0] * 64) return;
        A = kvn + (size_t)b0 * NQ * EMB;
        ridx = g_kidx + b0 * NK + rloc;
    }
    const __half* B = wt + (size_t)z * EMB * EMB + bn * EMB;
    float c[2][8][4];
    gemm16_mainloop(A, ridx, B, c, smqkv);

    const int tid = threadIdx.x, lane = tid & 31, wid = tid >> 5;
    const int wm = wid & 3, wn = wid >> 2, g = lane >> 2, t = lane & 3;
    const float* bias = (z == 0) ? bq : (z == 1) ? bk : bv;
    const float scale = (z == 0) ? 0.1803368801111244f : 1.0f;  // 0.125*log2(e)

    if (z < 2) {
        #pragma unroll
        for (int mt = 0; mt < 2; mt++) {
            #pragma unroll
            for (int nt = 0; nt < 8; nt++) {
                int m   = (int)bm + wm * 32 + mt * 16 + g;
                int col = (int)bn + wn * 64 + nt * 8 + 2 * t;
                float b0_ = bias[col], b1_ = bias[col + 1];
                float v0 = (c[mt][nt][0] + b0_) * scale;
                float v1 = (c[mt][nt][1] + b1_) * scale;
                float v2 = (c[mt][nt][2] + b0_) * scale;
                float v3 = (c[mt][nt][3] + b1_) * scale;
                __half* dst = (z == 0) ? q : k;
                *(half2*)(dst + (size_t)m * EMB + col) = __floats2half2_rn(v0, v1);
                *(half2*)(dst + (size_t)(m + 8) * EMB + col) = __floats2half2_rn(v2, v3);
            }
        }
    } else {
        __half* smT = (__half*)smqkv;
        __syncthreads();
        #pragma unroll
        for (int mt = 0; mt < 2; mt++) {
            #pragma unroll
            for (int nt = 0; nt < 8; nt++) {
                int m   = wm * 32 + mt * 16 + g;
                int col = wn * 64 + nt * 8 + 2 * t;
                float b0_ = bias[(int)bn + col], b1_ = bias[(int)bn + col + 1];
                smT[col * 136 + m]           = __float2half_rn(c[mt][nt][0] + b0_);
                smT[(col + 1) * 136 + m]     = __float2half_rn(c[mt][nt][1] + b1_);
                smT[col * 136 + m + 8]       = __float2half_rn(c[mt][nt][2] + b0_);
                smT[(col + 1) * 136 + m + 8] = __float2half_rn(c[mt][nt][3] + b1_);
            }
        }
        __syncthreads();
        int col = tid >> 1;
        int mo  = (tid & 1) * 64;
        int gc  = (int)bn + col;
        int h = gc >> 6, d = gc & 63;
        size_t orow = ((size_t)(b0 * NH + h) * HD + d) * NK + (size_t)rloc + mo;
        const uint4* srcp = (const uint4*)(smT + col * 136 + mo);
        uint4* dstp = (uint4*)(vt + orow);
        #pragma unroll
        for (int j = 0; j < 8; j++) dstp[j] = srcp[j];
    }
}

__global__ void __launch_bounds__(256, 2) proj_o_kernel(
        int b0,
        const __half* __restrict__ ctx, const __half* __restrict__ wt,
        const float* __restrict__ bo, float* __restrict__ out) {
    extern __shared__ __align__(16) char smo[];
    const size_t bm = (size_t)b0 * NQ + (size_t)blockIdx.y * 128;
    const size_t bn = (size_t)blockIdx.x * 128;
    float c[2][8][4];
    gemm16_mainloop(ctx + bm * EMB, nullptr,
                    wt + 3ull * EMB * EMB + bn * EMB, c, smo);

    const int tid = threadIdx.x, lane = tid & 31, wid = tid >> 5;
    const int wm = wid & 3, wn = wid >> 2, g = lane >> 2, t = lane & 3;
    #pragma unroll
    for (int mt = 0; mt < 2; mt++) {
        #pragma unroll
        for (int nt = 0; nt < 8; nt++) {
            int m   = (int)bm + wm * 32 + mt * 16 + g;
            int col = (int)bn + wn * 64 + nt * 8 + 2 * t;
            float b0_ = bo[col], b1_ = bo[col + 1];
            *(float2*)(out + (size_t)m * EMB + col) =
                make_float2(c[mt][nt][0] + b0_, c[mt][nt][1] + b1_);
            *(float2*)(out + (size_t)(m + 8) * EMB + col) =
                make_float2(c[mt][nt][2] + b0_, c[mt][nt][3] + b1_);
        }
    }
}

// ---------------- fused flash attention (R15 internals, per-batch) -------------
#define FATTN_SMEM 41472
__global__ void __launch_bounds__(256, 2) fattn_kernel(
        int b0,
        const __half* __restrict__ Qp, const __half* __restrict__ Kp,
        const __half* __restrict__ Vtp,
        const unsigned long long* __restrict__ mbits,
        __half* __restrict__ ctx) {
    extern __shared__ __align__(16) __half smd[];
    __half* KsB = smd;
    __half* VsB = smd + 9216;

    const int tid = threadIdx.x;
    const int lane = tid & 31, w = tid >> 5;
    const int g = lane >> 2, t = lane & 3;
    const int qt = blockIdx.x;
    const int b = b0, h = blockIdx.y;
    const int bh = b * NH + h;
    const int row0 = w * 16 + g, row1 = row0 + 8;
    const int nkt = g_nkt[b];

    const uint32_t ks_smem = sptr(KsB);
    const uint32_t vs_smem = sptr(VsB);
    const uint32_t lrow = ((lane & 16) ? 8 : 0) + (lane & 7);
    const uint32_t k_base = ks_smem + lrow * 144 + ((lane & 8) ? 16 : 0);
    const uint32_t v_base = vs_smem + lrow * 144 + ((lane & 8) ? 16 : 0);

    for (int idx = tid; idx < 2 * 16 * 72; idx += 256) {
        int bufr = idx / 72, col = idx % 72;
        int buf = bufr >> 4, row = 64 + (bufr & 15);
        VsB[buf * 5760 + row * 72 + col] =
            (row == 64) ? __float2half(1.0f) : __float2half(0.0f);
    }

    uint32_t qa[4][4];
    {
        const __half* q0 = Qp + (size_t)(b * NQ + qt * 128 + row0) * EMB + h * HD;
        const __half* q1 = Qp + (size_t)(b * NQ + qt * 128 + row1) * EMB + h * HD;
        #pragma unroll
        for (int ks = 0; ks < 4; ks++) {
            qa[ks][0] = *(const uint32_t*)(q0 + ks * 16 + 2 * t);
            qa[ks][1] = *(const uint32_t*)(q1 + ks * 16 + 2 * t);
            qa[ks][2] = *(const uint32_t*)(q0 + ks * 16 + 2 * t + 8);
            qa[ks][3] = *(const uint32_t*)(q1 + ks * 16 + 2 * t + 8);
        }
    }

    float m0 = -40.0f, m1 = -40.0f;
    float acc[9][4];
    #pragma unroll
    for (int nt = 0; nt < 9; nt++)
        #pragma unroll
        for (int j = 0; j < 4; j++) acc[nt][j] = 0.0f;

    const unsigned long long* mb0 =
        mbits + ((size_t)b * NQ + qt * 128 + row0) * (NK / 64);
    const unsigned long long* mb1 =
        mbits + ((size_t)b * NQ + qt * 128 + row1) * (NK / 64);

    const __half* Kbase  = Kp + ((size_t)b * NK) * EMB + h * HD;
    const __half* Vtbase = Vtp + (size_t)bh * HD * NK;

    if (nkt > 0) {
        #pragma unroll
        for (int i = 0; i < 2; i++) {
            int s = tid + i * 256;
            int r = s >> 3, f = s & 7;
            CP16(ks_smem + r * 144 + f * 16, Kbase + (size_t)r * EMB + f * 8);
            CP16(vs_smem + r * 144 + f * 16, Vtbase + (size_t)r * NK + f * 8);
        }
        CP_COMMIT();
    }

    for (int kt = 0; kt < nkt; kt++) {
        const int buf = kt & 1;
        unsigned long long w0 = mb0[kt], w1 = mb1[kt];

        uint32_t um[4][4];
        #pragma unroll
        for (int ks = 0; ks < 4; ks++) {
            int cA = ks * 16 + 2 * t;
            int cB = cA + 8;
            uint32_t a0 = (uint32_t)(w0 >> cA) & 3u;
            uint32_t a1 = (uint32_t)(w1 >> cA) & 3u;
            uint32_t b0_ = (uint32_t)(w0 >> cB) & 3u;
            uint32_t b1_ = (uint32_t)(w1 >> cB) & 3u;
            um[ks][0] = ((a0 & 1u) * 0xFFFFu) | ((a0 >> 1) * 0xFFFF0000u);
            um[ks][1] = ((a1 & 1u) * 0xFFFFu) | ((a1 >> 1) * 0xFFFF0000u);
            um[ks][2] = ((b0_ & 1u) * 0xFFFFu) | ((b0_ >> 1) * 0xFFFF0000u);
            um[ks][3] = ((b1_ & 1u) * 0xFFFFu) | ((b1_ >> 1) * 0xFFFF0000u);
        }

        CP_WAIT0();
        __syncthreads();

        if (kt + 1 < nkt) {
            int k0n = (kt + 1) * 64;
            int nbuf = buf ^ 1;
            #pragma unroll
            for (int i = 0; i < 2; i++) {
                int s = tid + i * 256;
                int r = s >> 3, f = s & 7;
                CP16(ks_smem + nbuf * 9216 + r * 144 + f * 16,
                     Kbase + (size_t)(k0n + r) * EMB + f * 8);
                CP16(vs_smem + nbuf * 11520 + r * 144 + f * 16,
                     Vtbase + (size_t)r * NK + k0n + f * 8);
            }
            CP_COMMIT();
        }

        float sc[8][4];
        #pragma unroll
        for (int nt = 0; nt < 8; nt++)
            #pragma unroll
            for (int j = 0; j < 4; j++) sc[nt][j] = 0.0f;
        const uint32_t kb = k_base + buf * 9216;
        #pragma unroll
        for (int ks = 0; ks < 4; ks++) {
            uint32_t bf[8][2];
            #pragma unroll
            for (int p = 0; p < 4; p++)
                LDSM4(bf[2*p][0], bf[2*p][1], bf[2*p+1][0], bf[2*p+1][1],
                      kb + p * 16 * 144 + ks * 32);
            #pragma unroll
            for (int nt = 0; nt < 8; nt++)
                MMA_F16(sc[nt], qa[ks], bf[nt]);
        }

        float tm0 = -1e30f, tm1 = -1e30f;
        #pragma unroll
        for (int nt = 0; nt < 8; nt++) {
            tm0 = fmaxf(tm0, fmaxf(sc[nt][0], sc[nt][1]));
            tm1 = fmaxf(tm1, fmaxf(sc[nt][2], sc[nt][3]));
        }
        tm0 = fmaxf(tm0, __shfl_xor_sync(0xffffffffu, tm0, 1));
        tm0 = fmaxf(tm0, __shfl_xor_sync(0xffffffffu, tm0, 2));
        tm1 = fmaxf(tm1, __shfl_xor_sync(0xffffffffu, tm1, 1));
        tm1 = fmaxf(tm1, __shfl_xor_sync(0xffffffffu, tm1, 2));

        float mn0 = fmaxf(m0, tm0), mn1 = fmaxf(m1, tm1);
        if (__any_sync(0xffffffffu, (mn0 > m0) | (mn1 > m1))) {
            float corr0 = exp2f(m0 - mn0);
            float corr1 = exp2f(m1 - mn1);
            #pragma unroll
            for (int nt = 0; nt < 9; nt++) {
                acc[nt][0] *= corr0; acc[nt][1] *= corr0;
                acc[nt][2] *= corr1; acc[nt][3] *= corr1;
            }
            m0 = mn0;  m1 = mn1;
        }

        uint32_t pfrag[4][4];
        #pragma unroll
        for (int ks = 0; ks < 4; ks++) {
            half2 h00 = __floats2half2_rn(sc[2*ks][0] - m0, sc[2*ks][1] - m0);
            half2 h01 = __floats2half2_rn(sc[2*ks][2] - m1, sc[2*ks][3] - m1);
            half2 h10 = __floats2half2_rn(sc[2*ks+1][0] - m0, sc[2*ks+1][1] - m0);
            half2 h11 = __floats2half2_rn(sc[2*ks+1][2] - m1, sc[2*ks+1][3] - m1);
            pfrag[ks][0] = h2ex2(*(uint32_t*)&h00) & um[ks][0];
            pfrag[ks][1] = h2ex2(*(uint32_t*)&h01) & um[ks][1];
            pfrag[ks][2] = h2ex2(*(uint32_t*)&h10) & um[ks][2];
            pfrag[ks][3] = h2ex2(*(uint32_t*)&h11) & um[ks][3];
        }

        const uint32_t vb = v_base + buf * 11520;
        #pragma unroll
        for (int ks = 0; ks < 4; ks++) {
            uint32_t bv[10][2];
            #pragma unroll
            for (int p = 0; p < 5; p++)
                LDSM4(bv[2*p][0], bv[2*p][1], bv[2*p+1][0], bv[2*p+1][1],
                      vb + p * 16 * 144 + ks * 32);
            #pragma unroll
            for (int nt = 0; nt < 9; nt++)
                MMA_F16(acc[nt], pfrag[ks], bv[nt]);
        }
    }

    float l0 = __shfl_sync(0xffffffffu, acc[8][0], lane & 28);
    float l1 = __shfl_sync(0xffffffffu, acc[8][2], lane & 28);
    float inv0 = (l0 > 0.0f) ? (1.0f / l0) : 0.0f;
    float inv1 = (l1 > 0.0f) ? (1.0f / l1) : 0.0f;
    __half* o0 = ctx + (size_t)(b * NQ + qt * 128 + row0) * EMB + h * HD;
    __half* o1 = ctx + (size_t)(b * NQ + qt * 128 + row1) * EMB + h * HD;
    #pragma unroll
    for (int nt = 0; nt < 8; nt++) {
        int c0 = nt * 8 + 2 * t;
        *(half2*)(o0 + c0) = __floats2half2_rn(acc[nt][0] * inv0, acc[nt][1] * inv0);
        *(half2*)(o1 + c0) = __floats2half2_rn(acc[nt][2] * inv1, acc[nt][3] * inv1);
    }
}

// ---------------- mask dtype sniff ---------------------------------------------
__global__ void detect_mask_kernel(const unsigned char* kvm_raw,
                                   const unsigned char* spm_raw) {
    __shared__ int found[2];
    if (threadIdx.x == 0) { found[0] = 0; found[1] = 0; }
    __syncthreads();
    for (int i = threadIdx.x; i < 8192; i += blockDim.x) {
        if ((i & 3) != 0) {
            if (kvm_raw[i]) atomicOr(&found[0], 1);
            if (spm_raw[i]) atomicOr(&found[1], 1);
        }
    }
    __syncthreads();
    if (threadIdx.x == 0) { g_is_byte[0] = found[0]; g_is_byte[1] = found[1]; }
}

// ---------------- kv_mask stream compaction -------------------------------------
__global__ void compact_idx_kernel(const void* kvm_raw) {
    const int b = blockIdx.x;
    const int tid = threadIdx.x;
    const int lane = tid & 31, w = tid >> 5;
    __shared__ int base;
    __shared__ int wstart[8];
    __shared__ int wcnt[8];
    if (tid == 0) base = 0;
    __syncthreads();
    const bool kb = g_is_byte[0] != 0;
    for (int c0 = 0; c0 < NK; c0 += 256) {
        int kk = c0 + tid;
        bool v = kb ? (((const unsigned char*)kvm_raw)[b * NK + kk] != 0)
                    : (((const int*)kvm_raw)[b * NK + kk] != 0);
        unsigned bal = __ballot_sync(0xffffffffu, v);
        if (lane == 0) wcnt[w] = __popc(bal);
        __syncthreads();
        if (tid == 0) {
            int s = base;
            #pragma unroll
            for (int i = 0; i < 8; i++) { wstart[i] = s; s += wcnt[i]; }
            base = s;
        }
        __syncthreads();
        if (v)
            g_kidx[b * NK + wstart[w] + __popc(bal & ((1u << lane) - 1))] = kk;
        __syncthreads();
    }
    int nv = base;
    for (int c = nv + tid; c < NK; c += 256) g_kidx[b * NK + c] = 0;
    if (tid == 0) {
        g_nvalid[b] = nv;
        g_nkt[b] = (nv + 63) >> 6;
    }
}

// ---------------- sparse-mask bits (coalesced via smem), per batch --------------
__global__ void __launch_bounds__(256) mask_bits_kernel(int b0, const void* spm_raw) {
    __shared__ unsigned char sp_sm[2048];
    __shared__ uint32_t wb[64];
    const int bq = b0 * NQ + blockIdx.x;
    const int b = b0;
    const int tid = threadIdx.x;

    if (g_is_byte[1]) {
        const uint32_t* sp = (const uint32_t*)
            ((const unsigned char*)spm_raw + (size_t)bq * NK);
        for (int i = tid; i < 512; i += 256) {
            uint32_t v = sp[i];
            sp_sm[i * 4 + 0] = (v & 0x000000ffu) ? 1 : 0;
            sp_sm[i * 4 + 1] = (v & 0x0000ff00u) ? 1 : 0;
            sp_sm[i * 4 + 2] = (v & 0x00ff0000u) ? 1 : 0;
            sp_sm[i * 4 + 3] = (v & 0xff000000u) ? 1 : 0;
        }
    } else {
        const int* sp = (const int*)spm_raw + (size_t)bq * NK;
        for (int i = tid; i < 2048; i += 256)
            sp_sm[i] = sp[i] ? 1 : 0;
    }
    __syncthreads();

    const int nv = g_nvalid[b];
    const int* kidx = g_kidx + b * NK;
    #pragma unroll
    for (int i = 0; i < 8; i++) {
        int c = i * 256 + tid;
        bool bit = (c < nv) && (sp_sm[kidx[c]] != 0);
        unsigned bal = __ballot_sync(0xffffffffu, bit);
        if ((tid & 31) == 0) wb[i * 8 + (tid >> 5)] = bal;
    }
    __syncthreads();
    if (tid < 32) {
        int i = tid >> 2, wp = (tid & 3) * 2;
        uint64_t wv = (uint64_t)wb[i * 8 + wp] |
                      ((uint64_t)wb[i * 8 + wp + 1] << 32);
        g_mbits[(size_t)bq * 32 + tid] = wv;
    }
}

// ---------------- LayerNorm (warp-per-row, per batch) ---------------------------
__global__ void __launch_bounds__(256) lnorm_kernel(
        int b0,
        const float* __restrict__ xq, const float* __restrict__ xkv,
        const float* __restrict__ gq, const float* __restrict__ bq,
        const float* __restrict__ gkv, const float* __restrict__ bkv,
        __half* __restrict__ yq, __half* __restrict__ ykv) {
    const int row = b0 * NQ + blockIdx.x * 8 + (threadIdx.x >> 5);
    const int lane = threadIdx.x & 31;
    const float* x = blockIdx.y ? xkv : xq;
    const float* g = blockIdx.y ? gkv : gq;
    const float* b = blockIdx.y ? bkv : bq;
    __half* y      = blockIdx.y ? ykv : yq;

    const float4* xr = (const float4*)(x + (size_t)row * EMB);
    float4 v[4];
    float s = 0.0f, s2 = 0.0f;
    #pragma unroll
    for (int j = 0; j < 4; j++) {
        v[j] = xr[lane + 32 * j];
        s  += v[j].x + v[j].y + v[j].z + v[j].w;
        s2 += v[j].x*v[j].x + v[j].y*v[j].y + v[j].z*v[j].z + v[j].w*v[j].w;
    }
    #pragma unroll
    for (int o = 16; o > 0; o >>= 1) {
        s  += __shfl_xor_sync(0xffffffffu, s,  o);
        s2 += __shfl_xor_sync(0xffffffffu, s2, o);
    }
    float mu  = s * (1.0f / EMB);
    float var = s2 * (1.0f / EMB) - mu * mu;
    float inv = rsqrtf(var + 1e-5f);
    #pragma unroll
    for (int j = 0; j < 4; j++) {
        float4 gg = ((const float4*)g)[lane + 32 * j];
        float4 bb = ((const float4*)b)[lane + 32 * j];
        half2 h0 = __floats2half2_rn((v[j].x - mu) * inv * gg.x + bb.x,
                                     (v[j].y - mu) * inv * gg.y + bb.y);
        half2 h1 = __floats2half2_rn((v[j].z - mu) * inv * gg.z + bb.z,
                                     (v[j].w - mu) * inv * gg.w + bb.w);
        uint2 o2 = make_uint2(*(uint32_t*)&h0, *(uint32_t*)&h1);
        *(uint2*)(y + (size_t)row * EMB + (lane + 32 * j) * 4) = o2;
    }
}

// ---------------- weight transpose ------------------------------------------------
__global__ void wt_kernel(const float* __restrict__ Wq,
                          const float* __restrict__ Wk,
                          const float* __restrict__ Wv,
                          const float* __restrict__ Wo,
                          __half* __restrict__ Wt) {
    __shared__ float tile[32][33];
    int z = blockIdx.z;
    const float* W = (z == 0) ? Wq : (z == 1) ? Wk : (z == 2) ? Wv : Wo;
    __half* dst = Wt + (size_t)z * EMB * EMB;
    int bx = blockIdx.x * 32, by = blockIdx.y * 32;
    int tx = threadIdx.x, ty = threadIdx.y;
    #pragma unroll
    for (int i = 0; i < 4; i++)
        tile[ty + i * 8][tx] = W[(size_t)(by + ty + i * 8) * EMB + bx + tx];
    __syncthreads();
    #pragma unroll
    for (int i = 0; i < 4; i++)
        dst[(size_t)(bx + ty + i * 8) * EMB + by + tx] =
            __float2half_rn(tile[tx][ty + i * 8]);
}

// ---------------- launch ----------------------------------------------------------
extern "C" void kernel_launch(void* const* d_in, const int* in_sizes, int n_in,
                              void* d_out, int out_size) {
    const float* query     = (const float*)d_in[0];
    const float* key_value = (const float*)d_in[1];
    const void*  kvm_raw   = d_in[2];
    const void*  spm_raw   = d_in[3];
    const float* ln_q_g  = (const float*)d_in[4];
    const float* ln_q_b  = (const float*)d_in[5];
    const float* ln_kv_g = (const float*)d_in[6];
    const float* ln_kv_b = (const float*)d_in[7];
    const float* Wq = (const float*)d_in[8];
    const float* bq = (const float*)d_in[9];
    const float* Wk = (const float*)d_in[10];
    const float* bk = (const float*)d_in[11];
    const float* Wv = (const float*)d_in[12];
    const float* bv = (const float*)d_in[13];
    const float* Wo = (const float*)d_in[14];
    const float* bo = (const float*)d_in[15];
    float* out = (float*)d_out;

    void *p_qn, *p_kvn, *p_q, *p_k, *p_vt, *p_ctx, *p_wt, *p_mb;
    cudaGetSymbolAddress(&p_qn,  g_qn);
    cudaGetSymbolAddress(&p_kvn, g_kvn);
    cudaGetSymbolAddress(&p_q,   g_q);
    cudaGetSymbolAddress(&p_k,   g_k);
    cudaGetSymbolAddress(&p_vt,  g_vt);
    cudaGetSymbolAddress(&p_ctx, g_ctx);
    cudaGetSymbolAddress(&p_wt,  g_wt);
    cudaGetSymbolAddress(&p_mb,  g_mbits);

    cudaFuncSetAttribute(proj_qkv_kernel,
        cudaFuncAttributeMaxDynamicSharedMemorySize, GSMEM);
    cudaFuncSetAttribute(proj_o_kernel,
        cudaFuncAttributeMaxDynamicSharedMemorySize, GSMEM);
    cudaFuncSetAttribute(fattn_kernel,
        cudaFuncAttributeMaxDynamicSharedMemorySize, FATTN_SMEM);

    const bool fork = g_si.ok;
    cudaStream_t sm = fork ? g_si.s2 : (cudaStream_t)0;
    cudaStream_t sw = fork ? g_si.s3 : (cudaStream_t)0;

    if (fork) {
        cudaEventRecord(g_si.eFork, 0);
        cudaStreamWaitEvent(g_si.s2, g_si.eFork, 0);
        cudaStreamWaitEvent(g_si.s3, g_si.eFork, 0);
        for (int b = 1; b < BATCH; b++)
            cudaStreamWaitEvent(g_si.sb[b], g_si.eFork, 0);
    }

    // mask branch (s2): detect -> compact -> mask_bits per batch
    detect_mask_kernel<<<1, 256, 0, sm>>>((const unsigned char*)kvm_raw,
                                          (const unsigned char*)spm_raw);
    compact_idx_kernel<<<BATCH, 256, 0, sm>>>(kvm_raw);
    if (fork) cudaEventRecord(g_si.eCompact, g_si.s2);
    for (int b = 0; b < BATCH; b++) {
        mask_bits_kernel<<<NQ, 256, 0, sm>>>(b, spm_raw);
        if (fork) cudaEventRecord(g_si.eMaskB[b], g_si.s2);
    }

    // weight branch (s3)
    dim3 tb(32, 8), tg(16, 16, 4);
    wt_kernel<<<tg, tb, 0, sw>>>(Wq, Wk, Wv, Wo, (__half*)p_wt);
    if (fork) cudaEventRecord(g_si.eWt, g_si.s3);

    // batch pipelines
    dim3 lg(NQ / 8, 2);
    dim3 pg(EMB / 128, NQ / 128, 3);
    dim3 fg(NQ / 128, NH);
    dim3 og(EMB / 128, NQ / 128);
    for (int b = 0; b < BATCH; b++) {
        cudaStream_t st = fork ? g_si.sb[b] : (cudaStream_t)0;
        lnorm_kernel<<<lg, 256, 0, st>>>(b, query, key_value, ln_q_g, ln_q_b,
                                         ln_kv_g, ln_kv_b,
                                         (__half*)p_qn, (__half*)p_kvn);
        if (fork) {
            cudaStreamWaitEvent(st, g_si.eCompact, 0);
            cudaStreamWaitEvent(st, g_si.eWt, 0);
        }
        proj_qkv_kernel<<<pg, 256, GSMEM, st>>>(b,
            (const __half*)p_qn, (const __half*)p_kvn,
            (const __half*)p_wt, bq, bk, bv,
            (__half*)p_q, (__half*)p_k, (__half*)p_vt);
        if (fork) cudaStreamWaitEvent(st, g_si.eMaskB[b], 0);
        fattn_kernel<<<fg, 256, FATTN_SMEM, st>>>(b,
            (const __half*)p_q, (const __half*)p_k, (const __half*)p_vt,
            (const unsigned long long*)p_mb, (__half*)p_ctx);
        proj_o_kernel<<<og, 256, GSMEM, st>>>(b,
            (const __half*)p_ctx, (const __half*)p_wt, bo, out);
        if (fork && b > 0) cudaEventRecord(g_si.eDone[b - 1], st);
    }
    if (fork)
        for (int i = 0; i < 3; i++)
            cudaStreamWaitEvent(0, g_si.eDone[i], 0);
}